// round 1
// baseline (speedup 1.0000x reference)
#include <cuda_runtime.h>
#include <cuda_bf16.h>

// Problem constants (fixed by the reference)
#define BB 16
#define LL 256
#define DD 512
#define MELS 80
#define TF 3072            // T_MAX = L * MAXDUR
#define M2 (BB * TF)       // 49152 decoder rows
#define MEL_ELEMS (BB * MELS * TF)

// Scratch (device globals; no allocations allowed)
__device__ float g_x[BB * LL * DD];     // embed+pos     [B*L, D]   8 MB
__device__ float g_enc[BB * LL * DD];   // encoder out   [B*L, D]   8 MB
__device__ float g_dec[(size_t)M2 * DD];// decoder out   [B*T, D] 100 MB
__device__ int   g_tok[M2];             // frame -> token (-1 invalid)

// ---------------------------------------------------------------------------
// 1) x = emb_table[src] + pos_table[l]
// grid = B*L blocks, 128 threads (each thread one float4 of D=512)
__global__ void embed_kernel(const int* __restrict__ src,
                             const float* __restrict__ emb,
                             const float* __restrict__ pos) {
    int row = blockIdx.x;            // b*L + l
    int l = row & (LL - 1);
    int v = src[row];
    int d = threadIdx.x * 4;
    float4 e = *(const float4*)(emb + (size_t)v * DD + d);
    float4 p = *(const float4*)(pos + (size_t)l * DD + d);
    float4 o = make_float4(e.x + p.x, e.y + p.y, e.z + p.z, e.w + p.w);
    *(float4*)(g_x + (size_t)row * DD + d) = o;
}

// ---------------------------------------------------------------------------
// Generic 128x128x8 SGEMM: C = act(A @ W + bias)
// A: [M,K] row-major (or gathered rows via g_tok when GATHER)
// W: [K,N] row-major, C: [M,N]
// GATHER fast path: if g_tok[r0] < 0 the whole 128-row tile is invalid
// (invalid frames are a suffix per batch) -> C rows = relu(bias), skip K loop.
template <bool GATHER, bool RELU>
__global__ __launch_bounds__(256)
void gemm128(const float* __restrict__ A, const float* __restrict__ W,
             const float* __restrict__ bias, float* __restrict__ C,
             int M, int N, int K) {
    const int tid = threadIdx.x;
    const int r0 = blockIdx.y * 128;
    const int c0 = blockIdx.x * 128;

    const int rowb = (tid >> 4) * 8;   // 0..120
    const int colb = (tid & 15) * 8;   // 0..120

    if (GATHER) {
        if (g_tok[r0] < 0) {
            // whole tile invalid: dec row = relu(0 + b_dec)
            float v[8];
            #pragma unroll
            for (int j = 0; j < 8; j++) {
                float t = bias[c0 + colb + j];
                v[j] = RELU ? fmaxf(t, 0.0f) : t;
            }
            #pragma unroll
            for (int i = 0; i < 8; i++) {
                float* cp = C + (size_t)(r0 + rowb + i) * N + c0 + colb;
                #pragma unroll
                for (int j = 0; j < 8; j++) cp[j] = v[j];
            }
            return;
        }
    }

    __shared__ float As[8][128];
    __shared__ float Bs[8][128];

    // A-tile load mapping: thread -> one float4
    const int arow = tid >> 1;           // 0..127
    const int acol = (tid & 1) * 4;      // 0 or 4
    const float* Arow;
    if (GATHER) {
        int r = r0 + arow;
        int b = r / TF;
        int tk = g_tok[r];
        Arow = (tk >= 0) ? (g_enc + ((size_t)b * LL + tk) * DD) : nullptr;
    } else {
        Arow = A + (size_t)(r0 + arow) * K;
    }
    // B-tile load mapping
    const int brow = tid >> 5;           // 0..7
    const int bcol = (tid & 31) * 4;     // 0..124

    float acc[8][8];
    #pragma unroll
    for (int i = 0; i < 8; i++)
        #pragma unroll
        for (int j = 0; j < 8; j++) acc[i][j] = 0.0f;

    for (int kc = 0; kc < K; kc += 8) {
        float4 av = make_float4(0.f, 0.f, 0.f, 0.f);
        if (!GATHER || Arow) av = *(const float4*)(Arow + kc + acol);
        float4 bv = *(const float4*)(W + (size_t)(kc + brow) * N + c0 + bcol);

        As[acol + 0][arow] = av.x;
        As[acol + 1][arow] = av.y;
        As[acol + 2][arow] = av.z;
        As[acol + 3][arow] = av.w;
        *(float4*)(&Bs[brow][bcol]) = bv;
        __syncthreads();

        #pragma unroll
        for (int kk = 0; kk < 8; kk++) {
            float a[8], b[8];
            *(float4*)(a)     = *(const float4*)(&As[kk][rowb]);
            *(float4*)(a + 4) = *(const float4*)(&As[kk][rowb + 4]);
            *(float4*)(b)     = *(const float4*)(&Bs[kk][colb]);
            *(float4*)(b + 4) = *(const float4*)(&Bs[kk][colb + 4]);
            #pragma unroll
            for (int i = 0; i < 8; i++)
                #pragma unroll
                for (int j = 0; j < 8; j++)
                    acc[i][j] = fmaf(a[i], b[j], acc[i][j]);
        }
        __syncthreads();
    }

    // epilogue: bias (+ relu), store
    float bv[8];
    #pragma unroll
    for (int j = 0; j < 8; j++) bv[j] = bias[c0 + colb + j];
    #pragma unroll
    for (int i = 0; i < 8; i++) {
        float* cp = C + (size_t)(r0 + rowb + i) * N + c0 + colb;
        #pragma unroll
        for (int j = 0; j < 8; j++) {
            float t = acc[i][j] + bv[j];
            cp[j] = RELU ? fmaxf(t, 0.0f) : t;
        }
    }
}

// ---------------------------------------------------------------------------
// 3) duration head: dur_pred[row] = enc[row,:] . W_dur + b_dur
__global__ void dur_kernel(const float* __restrict__ W_dur,
                           const float* __restrict__ b_dur,
                           float* __restrict__ out_dur) {
    int row = blockIdx.x;  // 0..4095
    float acc = 0.0f;
    const float* e = g_enc + (size_t)row * DD;
    for (int d = threadIdx.x; d < DD; d += 128) acc += e[d] * W_dur[d];
    #pragma unroll
    for (int o = 16; o; o >>= 1) acc += __shfl_down_sync(0xffffffffu, acc, o);
    __shared__ float s[4];
    if ((threadIdx.x & 31) == 0) s[threadIdx.x >> 5] = acc;
    __syncthreads();
    if (threadIdx.x == 0)
        out_dur[row] = s[0] + s[1] + s[2] + s[3] + b_dur[0];
}

// ---------------------------------------------------------------------------
// 4) length regulator token map: per batch, inclusive scan of dur then
// tok[t] = #(csum <= t)  (== searchsorted right); -1 if past total duration.
__global__ void tok_kernel(const int* __restrict__ dur) {
    int b = blockIdx.x;
    __shared__ int cs[LL];
    int l = threadIdx.x;  // 256 threads == L
    cs[l] = dur[b * LL + l];
    __syncthreads();
    for (int off = 1; off < LL; off <<= 1) {
        int v = (l >= off) ? cs[l - off] : 0;
        __syncthreads();
        cs[l] += v;
        __syncthreads();
    }
    for (int t = threadIdx.x; t < TF; t += 256) {
        int lo = 0, hi = LL;
        while (lo < hi) {
            int mid = (lo + hi) >> 1;
            if (cs[mid] <= t) lo = mid + 1; else hi = mid;
        }
        g_tok[b * TF + t] = (lo < LL) ? lo : -1;
    }
}

// ---------------------------------------------------------------------------
// 6) generator + transpose: mel[b][m][t] = dec[b][t][:] . W_gen[:,m] + b_gen[m]
// Block: 64 frames x 80 mels; 256 threads; per-thread 4(t) x 5(m).
__global__ __launch_bounds__(256)
void gen_kernel(const float* __restrict__ Wg, const float* __restrict__ bg,
                float* __restrict__ mel) {
    __shared__ float As[16][64 + 1];  // [k][t]
    __shared__ float Bs[16][80];      // [k][m]
    const int tid = threadIdx.x;
    const int r0 = blockIdx.x * 64;   // global frame row base
    const int b = r0 / TF;
    const int t0 = r0 % TF;
    const int ty = tid & 15;          // t lane
    const int tx = tid >> 4;          // m group base (m = tx + 16*j)

    float acc[4][5];
    #pragma unroll
    for (int i = 0; i < 4; i++)
        #pragma unroll
        for (int j = 0; j < 5; j++) acc[i][j] = 0.0f;

    const int arow = tid >> 2;            // 0..63
    const int acol = (tid & 3) * 4;       // 0..12
    const float* Arow = g_dec + (size_t)(r0 + arow) * DD;

    for (int kc = 0; kc < DD; kc += 16) {
        float4 av = *(const float4*)(Arow + kc + acol);
        As[acol + 0][arow] = av.x;
        As[acol + 1][arow] = av.y;
        As[acol + 2][arow] = av.z;
        As[acol + 3][arow] = av.w;
        #pragma unroll
        for (int i = 0; i < 5; i++) {
            int idx = tid + i * 256;      // 0..1279
            int kr = idx / 80, mc = idx % 80;
            Bs[kr][mc] = Wg[(size_t)(kc + kr) * MELS + mc];
        }
        __syncthreads();
        #pragma unroll
        for (int kk = 0; kk < 16; kk++) {
            float a[4], w[5];
            #pragma unroll
            for (int i = 0; i < 4; i++) a[i] = As[kk][i * 16 + ty];
            #pragma unroll
            for (int j = 0; j < 5; j++) w[j] = Bs[kk][tx + 16 * j];
            #pragma unroll
            for (int i = 0; i < 4; i++)
                #pragma unroll
                for (int j = 0; j < 5; j++)
                    acc[i][j] = fmaf(a[i], w[j], acc[i][j]);
        }
        __syncthreads();
    }

    #pragma unroll
    for (int j = 0; j < 5; j++) {
        int m = tx + 16 * j;
        float bv = bg[m];
        #pragma unroll
        for (int i = 0; i < 4; i++) {
            int t = t0 + i * 16 + ty;     // consecutive t across ty -> coalesced
            mel[(size_t)b * MELS * TF + (size_t)m * TF + t] = acc[i][j] + bv;
        }
    }
}

// ---------------------------------------------------------------------------
extern "C" void kernel_launch(void* const* d_in, const int* in_sizes, int n_in,
                              void* d_out, int out_size) {
    const int*   src   = (const int*)d_in[0];
    const int*   durin = (const int*)d_in[1];
    // d_in[2] is T (== 3072, compile-time constant here)
    const float* emb   = (const float*)d_in[3];
    const float* pos   = (const float*)d_in[4];
    const float* W_enc = (const float*)d_in[5];
    const float* b_enc = (const float*)d_in[6];
    const float* W_dur = (const float*)d_in[7];
    const float* b_dur = (const float*)d_in[8];
    const float* W_dec = (const float*)d_in[9];
    const float* b_dec = (const float*)d_in[10];
    const float* W_gen = (const float*)d_in[11];
    const float* b_gen = (const float*)d_in[12];

    float* out     = (float*)d_out;
    float* mel     = out;                 // [B, MELS, T]
    float* dur_out = out + MEL_ELEMS;     // [B, L]

    float* gx;   cudaGetSymbolAddress((void**)&gx,   g_x);
    float* genc; cudaGetSymbolAddress((void**)&genc, g_enc);
    float* gdec; cudaGetSymbolAddress((void**)&gdec, g_dec);

    // 1) embed + positional
    embed_kernel<<<BB * LL, 128>>>(src, emb, pos);

    // 2) enc = relu(x @ W_enc + b_enc)   [4096 x 512 x 512]
    gemm128<false, true><<<dim3(DD / 128, (BB * LL) / 128), 256>>>(
        gx, W_enc, b_enc, genc, BB * LL, DD, DD);

    // 3) dur_pred = enc @ W_dur + b_dur
    dur_kernel<<<BB * LL, 128>>>(W_dur, b_dur, dur_out);

    // 4) token map (scan + searchsorted)
    tok_kernel<<<BB, LL>>>(durin);

    // 5) dec = relu(gather(enc) @ W_dec + b_dec)   [49152 x 512 x 512]
    gemm128<true, true><<<dim3(DD / 128, M2 / 128), 256>>>(
        nullptr, W_dec, b_dec, gdec, M2, DD, DD);

    // 6) mel = transpose(dec @ W_gen + b_gen)
    gen_kernel<<<M2 / 64, 256>>>(W_gen, b_gen, mel);
}

// round 3
// speedup vs baseline: 1.3205x; 1.3205x over previous
#include <cuda_runtime.h>
#include <cstdint>

// Problem constants
#define BB 16
#define LL 256
#define DD 512
#define MELS 80
#define TF 3072
#define M2 (BB * TF)
#define MEL_ELEMS (BB * MELS * TF)

// Scratch (device globals; zero-initialized at load, no allocations allowed)
__device__ float    g_x[BB * LL * DD];        // embed+pos [B*L, D]
__device__ float    g_enc[BB * LL * DD];      // encoder out
__device__ float    g_dec[(size_t)M2 * DD];   // decoder out (valid tiles only)
__device__ int      g_tok[M2];                // frame -> token (-1 invalid)
__device__ unsigned g_WencT[DD * DD];         // W_enc^T tf32 bits [N][K]
__device__ unsigned g_WdecT[DD * DD];         // W_dec^T tf32 bits [N][K]
__device__ unsigned g_WgenT[128 * DD];        // W_gen^T tf32, padded to 128 rows (rows>=80 stay 0)
__device__ float    g_cvec[MELS];             // relu(b_dec) @ W_gen + b_gen

__device__ __forceinline__ unsigned f2tf32(float f) {
    unsigned u;
    asm("cvt.rna.tf32.f32 %0, %1;" : "=r"(u) : "f"(f));
    return u;
}
__device__ __forceinline__ void mma8(float c[4], const unsigned a[4], const unsigned b[2]) {
    asm volatile(
        "mma.sync.aligned.m16n8k8.row.col.f32.tf32.tf32.f32 "
        "{%0,%1,%2,%3}, {%4,%5,%6,%7}, {%8,%9}, {%0,%1,%2,%3};"
        : "+f"(c[0]), "+f"(c[1]), "+f"(c[2]), "+f"(c[3])
        : "r"(a[0]), "r"(a[1]), "r"(a[2]), "r"(a[3]), "r"(b[0]), "r"(b[1]));
}

// ---------------------------------------------------------------------------
__global__ void embed_kernel(const int* __restrict__ src,
                             const float* __restrict__ emb,
                             const float* __restrict__ pos) {
    int row = blockIdx.x;
    int l = row & (LL - 1);
    int v = src[row];
    int d = threadIdx.x * 4;
    float4 e = *(const float4*)(emb + (size_t)v * DD + d);
    float4 p = *(const float4*)(pos + (size_t)l * DD + d);
    *(float4*)(g_x + (size_t)row * DD + d) =
        make_float4(e.x + p.x, e.y + p.y, e.z + p.z, e.w + p.w);
}

// Weight transpose + tf32 convert: W [R][Ncols] -> WT [Ncols][R]
__global__ void transpose_w(const float* __restrict__ W, unsigned* __restrict__ WT,
                            int R, int Ncols) {
    __shared__ float t[32][33];
    int bx = blockIdx.x * 32, by = blockIdx.y * 32;
    int x = bx + threadIdx.x;
    for (int i = 0; i < 32; i += 8) {
        int y = by + threadIdx.y + i;
        if (x < Ncols && y < R) t[threadIdx.y + i][threadIdx.x] = W[(size_t)y * Ncols + x];
    }
    __syncthreads();
    int xo = by + threadIdx.x;
    for (int i = 0; i < 32; i += 8) {
        int yo = bx + threadIdx.y + i;
        if (xo < R && yo < Ncols)
            WT[(size_t)yo * R + xo] = f2tf32(t[threadIdx.x][threadIdx.y + i]);
    }
}

__global__ void cvec_kernel(const float* __restrict__ b_dec,
                            const float* __restrict__ W_gen,
                            const float* __restrict__ b_gen) {
    int m = threadIdx.x;
    if (m >= MELS) return;
    float acc = b_gen[m];
    for (int k = 0; k < DD; k++) acc += fmaxf(b_dec[k], 0.0f) * W_gen[k * MELS + m];
    g_cvec[m] = acc;
}

// ---------------------------------------------------------------------------
// tf32 mma.sync GEMM. CTA tile 128x128, 8 warps (2m x 4n), warp tile 64x32.
// Fragment-major smem: A frag = LDS.128, B frag = LDS.64.
// GATHER: A rows gathered via g_tok (dec GEMM); skip all-invalid tiles.
// GEN: A = dec rows, N=80 (padded weights), transposed mel output; invalid
//      tiles filled from g_cvec.
template <bool GATHER, bool GEN>
__global__ __launch_bounds__(256)
void mma_gemm(const float* __restrict__ A, const unsigned* __restrict__ WT,
              const float* __restrict__ bias, float* __restrict__ C) {
    extern __shared__ unsigned char sraw[];
    const int tid = threadIdx.x;
    const int lane = tid & 31, wid = tid >> 5;
    const int wm = wid & 1, wn = wid >> 1;
    const int r0 = blockIdx.y * 128;
    const int c0 = GEN ? 0 : blockIdx.x * 128;

    int bb = 0, t0 = 0;
    if (GEN) {
        bb = r0 / TF; t0 = r0 % TF;
        if (g_tok[r0] < 0) {
            // invalid suffix tile: mel[:, t] = cvec
            float* mp = C + (size_t)bb * MELS * TF + t0;
            for (int idx = tid; idx < MELS * 128; idx += 256) {
                int m = idx >> 7, f = idx & 127;
                mp[(size_t)m * TF + f] = g_cvec[m];
            }
            return;
        }
    }
    if (GATHER && g_tok[r0] < 0) return;

    // staging source rows: thread pair per row
    const int srow = tid >> 1;
    const int kq0 = (tid & 1) * 16;  // float offset within 32-wide chunk
    const float* Arow;
    if (GATHER) {
        int r = r0 + srow;
        int tk = g_tok[r];
        Arow = (tk >= 0) ? (g_enc + ((size_t)(r / TF) * LL + tk) * DD) : nullptr;
    } else {
        Arow = A + (size_t)(r0 + srow) * DD;
    }
    const unsigned* Brow = WT + (size_t)(c0 + srow) * DD;

    // fragment-store indices
    const int a_mt = srow >> 4, a_lm = srow & 15;
    const int a_g = a_lm & 7, a_hi = a_lm >> 3;
    const int b_nt = srow >> 3, b_g = srow & 7;

    unsigned* const As0 = (unsigned*)sraw;                    // 16 KB
    unsigned* const Bs0 = (unsigned*)(sraw + 16384);          // 16 KB
    unsigned* const As1 = (unsigned*)(sraw + 32768);
    unsigned* const Bs1 = (unsigned*)(sraw + 49152);

    float c[4][4][4];
    #pragma unroll
    for (int mt = 0; mt < 4; mt++)
        #pragma unroll
        for (int nt = 0; nt < 4; nt++)
            #pragma unroll
            for (int j = 0; j < 4; j++) c[mt][nt][j] = 0.0f;

    float4 av[4];
    uint4  bv[4];

    #define LOADG(kc)                                                          \
        do {                                                                   \
            _Pragma("unroll")                                                  \
            for (int i = 0; i < 4; i++) {                                      \
                av[i] = Arow ? *(const float4*)(Arow + (kc) * 32 + kq0 + i * 4)\
                             : make_float4(0.f, 0.f, 0.f, 0.f);                \
                bv[i] = *(const uint4*)(Brow + (kc) * 32 + kq0 + i * 4);       \
            }                                                                  \
        } while (0)

    #define STAGE(As, Bs)                                                      \
        do {                                                                   \
            _Pragma("unroll")                                                  \
            for (int i = 0; i < 4; i++) {                                      \
                int k0 = kq0 + i * 4;                                          \
                int ks = k0 >> 3, khi = (k0 >> 2) & 1;                         \
                unsigned* ap = As + ((a_mt * 4 + ks) * 32 + a_g * 4) * 4 +     \
                               khi * 2 + a_hi;                                 \
                ap[0]  = f2tf32(av[i].x);                                      \
                ap[4]  = f2tf32(av[i].y);                                      \
                ap[8]  = f2tf32(av[i].z);                                      \
                ap[12] = f2tf32(av[i].w);                                      \
                unsigned* bp = Bs + ((b_nt * 4 + ks) * 32 + b_g * 4) * 2 + khi;\
                bp[0] = bv[i].x; bp[2] = bv[i].y;                              \
                bp[4] = bv[i].z; bp[6] = bv[i].w;                              \
            }                                                                  \
        } while (0)

    #define COMPUTE(As, Bs)                                                    \
        do {                                                                   \
            _Pragma("unroll")                                                  \
            for (int ks = 0; ks < 4; ks++) {                                   \
                unsigned af[4][4], bf[4][2];                                   \
                _Pragma("unroll")                                              \
                for (int mt = 0; mt < 4; mt++)                                 \
                    *(uint4*)af[mt] = *(const uint4*)(As +                     \
                        (((wm * 4 + mt) * 4 + ks) * 32 + lane) * 4);           \
                _Pragma("unroll")                                              \
                for (int nt = 0; nt < 4; nt++)                                 \
                    *(uint2*)bf[nt] = *(const uint2*)(Bs +                     \
                        (((wn * 4 + nt) * 4 + ks) * 32 + lane) * 2);           \
                _Pragma("unroll")                                              \
                for (int mt = 0; mt < 4; mt++)                                 \
                    _Pragma("unroll")                                          \
                    for (int nt = 0; nt < 4; nt++)                             \
                        mma8(c[mt][nt], af[mt], bf[nt]);                       \
            }                                                                  \
        } while (0)

    LOADG(0);
    STAGE(As0, Bs0);
    __syncthreads();

    #pragma unroll 2
    for (int kc = 0; kc < 16; kc++) {
        if (kc + 1 < 16) LOADG(kc + 1);
        if (kc & 1) COMPUTE(As1, Bs1); else COMPUTE(As0, Bs0);
        if (kc + 1 < 16) {
            if ((kc + 1) & 1) STAGE(As1, Bs1); else STAGE(As0, Bs0);
            __syncthreads();
        }
    }

    const int cg = lane >> 2, ct = lane & 3;

    if (!GEN) {
        // C[row][n] = relu(acc + bias[n]), N = DD
        #pragma unroll
        for (int mt = 0; mt < 4; mt++) {
            int row0 = r0 + wm * 64 + mt * 16 + cg;
            float* C0 = C + (size_t)row0 * DD;
            float* C1 = C0 + (size_t)8 * DD;
            #pragma unroll
            for (int nt = 0; nt < 4; nt++) {
                int n = c0 + wn * 32 + nt * 8 + ct * 2;
                float bv0 = __ldg(bias + n), bv1 = __ldg(bias + n + 1);
                float2 lo = make_float2(fmaxf(c[mt][nt][0] + bv0, 0.f),
                                        fmaxf(c[mt][nt][1] + bv1, 0.f));
                float2 hi = make_float2(fmaxf(c[mt][nt][2] + bv0, 0.f),
                                        fmaxf(c[mt][nt][3] + bv1, 0.f));
                *(float2*)(C0 + n) = lo;
                *(float2*)(C1 + n) = hi;
            }
        }
    } else {
        // transpose through smem, then coalesced mel[b][m][t] stores
        __syncthreads();
        float* sC = (float*)sraw;  // [80][128]
        #pragma unroll
        for (int mt = 0; mt < 4; mt++) {
            int f0 = wm * 64 + mt * 16 + cg;
            #pragma unroll
            for (int nt = 0; nt < 4; nt++) {
                int n = wn * 32 + nt * 8 + ct * 2;
                if (n < MELS) {
                    sC[n * 128 + f0]           = c[mt][nt][0];
                    sC[(n + 1) * 128 + f0]     = c[mt][nt][1];
                    sC[n * 128 + f0 + 8]       = c[mt][nt][2];
                    sC[(n + 1) * 128 + f0 + 8] = c[mt][nt][3];
                }
            }
        }
        __syncthreads();
        float* mp = C + (size_t)bb * MELS * TF + t0;
        #pragma unroll
        for (int i = 0; i < 10; i++) {
            int flat = tid + i * 256;      // 2560 = 80*32 float4s
            int m = flat >> 5, q = flat & 31;
            float4 v = *(float4*)(sC + m * 128 + q * 4);
            float bm = __ldg(bias + m);
            v.x += bm; v.y += bm; v.z += bm; v.w += bm;
            *(float4*)(mp + (size_t)m * TF + q * 4) = v;
        }
    }
    #undef LOADG
    #undef STAGE
    #undef COMPUTE
}

// ---------------------------------------------------------------------------
__global__ void dur_kernel(const float* __restrict__ W_dur,
                           const float* __restrict__ b_dur,
                           float* __restrict__ out_dur) {
    int row = blockIdx.x;
    float acc = 0.0f;
    const float* e = g_enc + (size_t)row * DD;
    for (int d = threadIdx.x; d < DD; d += 128) acc += e[d] * W_dur[d];
    #pragma unroll
    for (int o = 16; o; o >>= 1) acc += __shfl_down_sync(0xffffffffu, acc, o);
    __shared__ float s[4];
    if ((threadIdx.x & 31) == 0) s[threadIdx.x >> 5] = acc;
    __syncthreads();
    if (threadIdx.x == 0) out_dur[row] = s[0] + s[1] + s[2] + s[3] + b_dur[0];
}

__global__ void tok_kernel(const int* __restrict__ dur) {
    int b = blockIdx.x;
    __shared__ int cs[LL];
    int l = threadIdx.x;
    cs[l] = dur[b * LL + l];
    __syncthreads();
    for (int off = 1; off < LL; off <<= 1) {
        int v = (l >= off) ? cs[l - off] : 0;
        __syncthreads();
        cs[l] += v;
        __syncthreads();
    }
    for (int t = threadIdx.x; t < TF; t += 256) {
        int lo = 0, hi = LL;
        while (lo < hi) {
            int mid = (lo + hi) >> 1;
            if (cs[mid] <= t) lo = mid + 1; else hi = mid;
        }
        g_tok[b * TF + t] = (lo < LL) ? lo : -1;
    }
}

// ---------------------------------------------------------------------------
extern "C" void kernel_launch(void* const* d_in, const int* in_sizes, int n_in,
                              void* d_out, int out_size) {
    const int*   src   = (const int*)d_in[0];
    const int*   durin = (const int*)d_in[1];
    const float* emb   = (const float*)d_in[3];
    const float* pos   = (const float*)d_in[4];
    const float* W_enc = (const float*)d_in[5];
    const float* b_enc = (const float*)d_in[6];
    const float* W_dur = (const float*)d_in[7];
    const float* b_dur = (const float*)d_in[8];
    const float* W_dec = (const float*)d_in[9];
    const float* b_dec = (const float*)d_in[10];
    const float* W_gen = (const float*)d_in[11];
    const float* b_gen = (const float*)d_in[12];

    float* out     = (float*)d_out;
    float* mel     = out;
    float* dur_out = out + MEL_ELEMS;

    float* gx;   cudaGetSymbolAddress((void**)&gx,   g_x);
    float* genc; cudaGetSymbolAddress((void**)&genc, g_enc);
    float* gdec; cudaGetSymbolAddress((void**)&gdec, g_dec);
    unsigned* wet; cudaGetSymbolAddress((void**)&wet, g_WencT);
    unsigned* wdt; cudaGetSymbolAddress((void**)&wdt, g_WdecT);
    unsigned* wgt; cudaGetSymbolAddress((void**)&wgt, g_WgenT);

    const int SMEM = 65536;
    cudaFuncSetAttribute(mma_gemm<false, false>,
                         cudaFuncAttributeMaxDynamicSharedMemorySize, SMEM);
    cudaFuncSetAttribute(mma_gemm<true, false>,
                         cudaFuncAttributeMaxDynamicSharedMemorySize, SMEM);
    cudaFuncSetAttribute(mma_gemm<false, true>,
                         cudaFuncAttributeMaxDynamicSharedMemorySize, SMEM);

    dim3 tb(32, 8);
    transpose_w<<<dim3(16, 16), tb>>>(W_enc, wet, DD, DD);
    transpose_w<<<dim3(16, 16), tb>>>(W_dec, wdt, DD, DD);
    transpose_w<<<dim3(3, 16),  tb>>>(W_gen, wgt, DD, MELS);  // rows 80..127 stay zero
    cvec_kernel<<<1, 128>>>(b_dec, W_gen, b_gen);

    embed_kernel<<<BB * LL, 128>>>(src, emb, pos);

    // enc = relu(x @ W_enc + b_enc)
    mma_gemm<false, false><<<dim3(4, (BB * LL) / 128), 256, SMEM>>>(gx, wet, b_enc, genc);

    dur_kernel<<<BB * LL, 128>>>(W_dur, b_dur, dur_out);
    tok_kernel<<<BB, LL>>>(durin);

    // dec = relu(gather(enc) @ W_dec + b_dec), valid tiles only
    mma_gemm<true, false><<<dim3(4, M2 / 128), 256, SMEM>>>(nullptr, wdt, b_dec, gdec);

    // mel = transpose(dec @ W_gen + b_gen); invalid tiles -> cvec
    mma_gemm<false, true><<<dim3(1, M2 / 128), 256, SMEM>>>(gdec, wgt, b_gen, mel);
}

// round 4
// speedup vs baseline: 3.4393x; 2.6045x over previous
#include <cuda_runtime.h>
#include <cstdint>

// Problem constants
#define BB 16
#define LL 256
#define DD 512
#define MELS 80
#define TF 3072
#define M2 (BB * TF)
#define MEL_ELEMS (BB * MELS * TF)
#define KC_N (DD / 32)          // 16 K-chunks of 32
#define FRAG_WORDS 4096         // one 128n x 32k fragment block = 16 KB

// Scratch (device globals; no allocations allowed)
__device__ float    g_x[BB * LL * DD];          // embed+pos
__device__ float    g_enc[BB * LL * DD];        // encoder out
__device__ float    g_dec[(size_t)M2 * DD];     // decoder out
__device__ int      g_tok[M2];                  // frame -> token (-1 invalid)
__device__ unsigned g_WencF[4 * KC_N * FRAG_WORDS];  // fragment-order tf32 weights
__device__ unsigned g_WdecF[4 * KC_N * FRAG_WORDS];
__device__ unsigned g_WgenF[1 * KC_N * FRAG_WORDS];  // n>=80 zero-padded
__device__ float    g_cvec[MELS];               // relu(b_dec) @ W_gen + b_gen

__device__ __forceinline__ unsigned f2tf32(float f) {
    unsigned u;
    asm("cvt.rna.tf32.f32 %0, %1;" : "=r"(u) : "f"(f));
    return u;
}
__device__ __forceinline__ void mma8(float c[4], const unsigned a[4], const unsigned b[2]) {
    asm volatile(
        "mma.sync.aligned.m16n8k8.row.col.f32.tf32.tf32.f32 "
        "{%0,%1,%2,%3}, {%4,%5,%6,%7}, {%8,%9}, {%0,%1,%2,%3};"
        : "+f"(c[0]), "+f"(c[1]), "+f"(c[2]), "+f"(c[3])
        : "r"(a[0]), "r"(a[1]), "r"(a[2]), "r"(a[3]), "r"(b[0]), "r"(b[1]));
}

// ---------------------------------------------------------------------------
__global__ void embed_kernel(const int* __restrict__ src,
                             const float* __restrict__ emb,
                             const float* __restrict__ pos) {
    int row = blockIdx.x;
    int l = row & (LL - 1);
    int v = src[row];
    int d = threadIdx.x * 4;
    float4 e = *(const float4*)(emb + (size_t)v * DD + d);
    float4 p = *(const float4*)(pos + (size_t)l * DD + d);
    *(float4*)(g_x + (size_t)row * DD + d) =
        make_float4(e.x + p.x, e.y + p.y, e.z + p.z, e.w + p.w);
}

// ---------------------------------------------------------------------------
// Build fragment-order tf32 weights from W [K=DD rows][Ncols] (row-major).
// Block index = ntile * KC_N + kc; each block is FRAG_WORDS words:
//   within: r = w&1, lane = (w>>1)&31, ks = (w>>6)&3, nt = w>>8 (0..15)
//   n = ntile*128 + nt*8 + (lane>>2);  k = kc*32 + ks*8 + (lane&3) + 4*r
__global__ void wfrag_kernel(const float* __restrict__ W, unsigned* __restrict__ WF,
                             int Ncols) {
    int blk = blockIdx.x;
    int ntile = blk / KC_N, kc = blk % KC_N;
    unsigned* out = WF + (size_t)blk * FRAG_WORDS;
    for (int w = threadIdx.x; w < FRAG_WORDS; w += 256) {
        int r = w & 1, lane = (w >> 1) & 31, ks = (w >> 6) & 3, nt = w >> 8;
        int n = ntile * 128 + nt * 8 + (lane >> 2);
        int k = kc * 32 + ks * 8 + (lane & 3) + 4 * r;
        out[w] = (n < Ncols) ? f2tf32(W[(size_t)k * Ncols + n]) : 0u;
    }
}

// cvec[m] = relu(b_dec) . W_gen[:,m] + b_gen[m]; one block per m, warp reduce
__global__ void cvec_kernel(const float* __restrict__ b_dec,
                            const float* __restrict__ W_gen,
                            const float* __restrict__ b_gen) {
    int m = blockIdx.x;
    float acc = 0.0f;
    for (int k = threadIdx.x; k < DD; k += 128)
        acc += fmaxf(b_dec[k], 0.0f) * W_gen[k * MELS + m];
    #pragma unroll
    for (int o = 16; o; o >>= 1) acc += __shfl_down_sync(0xffffffffu, acc, o);
    __shared__ float s[4];
    if ((threadIdx.x & 31) == 0) s[threadIdx.x >> 5] = acc;
    __syncthreads();
    if (threadIdx.x == 0) g_cvec[m] = s[0] + s[1] + s[2] + s[3] + b_gen[m];
}

// ---------------------------------------------------------------------------
// tf32 mma.sync GEMM, CTA 128x128, 8 warps (2m x 4n), warp 64x32.
// A staged row-major padded to 36 words/row (conflict-free STS.128 + LDS.32).
// B staged as contiguous precomputed fragment blocks (conflict-free copies).
#define A_PITCH 36
#define A_BYTES (128 * A_PITCH * 4)   // 18432
#define B_BYTES (FRAG_WORDS * 4)      // 16384
#define SMEM_TOTAL (2 * A_BYTES + 2 * B_BYTES)  // 70912 -> round up 71680

template <bool GATHER, bool GEN>
__global__ __launch_bounds__(256)
void mma_gemm(const float* __restrict__ A, const unsigned* __restrict__ WF,
              const float* __restrict__ bias, float* __restrict__ C) {
    extern __shared__ unsigned char sraw[];
    const int tid = threadIdx.x;
    const int lane = tid & 31, wid = tid >> 5;
    const int wm = wid & 1, wn = wid >> 1;
    const int r0 = blockIdx.y * 128;
    const int ntile = GEN ? 0 : blockIdx.x;

    int bb = 0, t0 = 0;
    if (GEN) {
        bb = r0 / TF; t0 = r0 % TF;
        if (g_tok[r0] < 0) {
            float* mp = C + (size_t)bb * MELS * TF + t0;
            for (int idx = tid; idx < MELS * 128; idx += 256) {
                int m = idx >> 7, f = idx & 127;
                mp[(size_t)m * TF + f] = g_cvec[m];
            }
            return;
        }
    }
    if (GATHER && g_tok[r0] < 0) return;

    unsigned* const As0 = (unsigned*)sraw;
    unsigned* const As1 = (unsigned*)(sraw + A_BYTES);
    unsigned* const Bs0 = (unsigned*)(sraw + 2 * A_BYTES);
    unsigned* const Bs1 = (unsigned*)(sraw + 2 * A_BYTES + B_BYTES);

    // staging: thread pair per A row; B = contiguous block copy
    const int srow = tid >> 1;
    const int kq0 = (tid & 1) * 16;
    const float* Arow;
    if (GATHER) {
        int r = r0 + srow;
        int tk = g_tok[r];
        Arow = (tk >= 0) ? (g_enc + ((size_t)(r / TF) * LL + tk) * DD) : nullptr;
    } else {
        Arow = A + (size_t)(r0 + srow) * DD;
    }
    const unsigned* WFbase = WF + (size_t)ntile * KC_N * FRAG_WORDS;

    float c[4][4][4];
    #pragma unroll
    for (int mt = 0; mt < 4; mt++)
        #pragma unroll
        for (int nt = 0; nt < 4; nt++)
            #pragma unroll
            for (int j = 0; j < 4; j++) c[mt][nt][j] = 0.0f;

    float4 av[4];
    uint4  bv[4];

    #define LOADG(kc)                                                           \
        do {                                                                    \
            const unsigned* bsrc = WFbase + (size_t)(kc) * FRAG_WORDS;          \
            _Pragma("unroll")                                                   \
            for (int i = 0; i < 4; i++) {                                       \
                av[i] = Arow ? *(const float4*)(Arow + (kc) * 32 + kq0 + i * 4) \
                             : make_float4(0.f, 0.f, 0.f, 0.f);                 \
                bv[i] = *(const uint4*)(bsrc + (tid + i * 256) * 4);            \
            }                                                                   \
        } while (0)

    #define STAGE(As, Bs)                                                       \
        do {                                                                    \
            _Pragma("unroll")                                                   \
            for (int i = 0; i < 4; i++) {                                       \
                *(uint4*)(As + srow * A_PITCH + kq0 + i * 4) =                  \
                    make_uint4(f2tf32(av[i].x), f2tf32(av[i].y),                \
                               f2tf32(av[i].z), f2tf32(av[i].w));               \
                *(uint4*)(Bs + (tid + i * 256) * 4) = bv[i];                    \
            }                                                                   \
        } while (0)

    #define COMPUTE(As, Bs)                                                     \
        do {                                                                    \
            const int g_ = lane >> 2, ct_ = lane & 3;                           \
            _Pragma("unroll")                                                   \
            for (int ks = 0; ks < 4; ks++) {                                    \
                unsigned af[4][4], bf[4][2];                                    \
                _Pragma("unroll")                                               \
                for (int mt = 0; mt < 4; mt++) {                                \
                    const unsigned* ap =                                        \
                        As + (wm * 64 + mt * 16 + g_) * A_PITCH + ks * 8 + ct_; \
                    af[mt][0] = ap[0];                                          \
                    af[mt][1] = ap[8 * A_PITCH];                                \
                    af[mt][2] = ap[4];                                          \
                    af[mt][3] = ap[8 * A_PITCH + 4];                            \
                }                                                               \
                _Pragma("unroll")                                               \
                for (int nt = 0; nt < 4; nt++)                                  \
                    *(uint2*)bf[nt] = *(const uint2*)(Bs +                      \
                        (((wn * 4 + nt) * 4 + ks) * 32 + lane) * 2);            \
                _Pragma("unroll")                                               \
                for (int mt = 0; mt < 4; mt++)                                  \
                    _Pragma("unroll")                                           \
                    for (int nt = 0; nt < 4; nt++)                              \
                        mma8(c[mt][nt], af[mt], bf[nt]);                        \
            }                                                                   \
        } while (0)

    LOADG(0);
    STAGE(As0, Bs0);
    __syncthreads();

    #pragma unroll 2
    for (int kc = 0; kc < KC_N; kc++) {
        if (kc + 1 < KC_N) LOADG(kc + 1);
        if (kc & 1) COMPUTE(As1, Bs1); else COMPUTE(As0, Bs0);
        if (kc + 1 < KC_N) {
            if ((kc + 1) & 1) STAGE(As1, Bs1); else STAGE(As0, Bs0);
            __syncthreads();
        }
    }

    const int cg = lane >> 2, ct = lane & 3;

    if (!GEN) {
        #pragma unroll
        for (int mt = 0; mt < 4; mt++) {
            int row0 = r0 + wm * 64 + mt * 16 + cg;
            float* C0 = C + (size_t)row0 * DD;
            float* C1 = C0 + (size_t)8 * DD;
            #pragma unroll
            for (int nt = 0; nt < 4; nt++) {
                int n = ntile * 128 + wn * 32 + nt * 8 + ct * 2;
                float bv0 = __ldg(bias + n), bv1 = __ldg(bias + n + 1);
                *(float2*)(C0 + n) = make_float2(fmaxf(c[mt][nt][0] + bv0, 0.f),
                                                 fmaxf(c[mt][nt][1] + bv1, 0.f));
                *(float2*)(C1 + n) = make_float2(fmaxf(c[mt][nt][2] + bv0, 0.f),
                                                 fmaxf(c[mt][nt][3] + bv1, 0.f));
            }
        }
    } else {
        __syncthreads();
        float* sC = (float*)sraw;  // [80][128] = 40 KB, fits
        #pragma unroll
        for (int mt = 0; mt < 4; mt++) {
            int f0 = wm * 64 + mt * 16 + cg;
            #pragma unroll
            for (int nt = 0; nt < 4; nt++) {
                int n = wn * 32 + nt * 8 + ct * 2;
                if (n < MELS) {
                    sC[n * 128 + f0]           = c[mt][nt][0];
                    sC[(n + 1) * 128 + f0]     = c[mt][nt][1];
                    sC[n * 128 + f0 + 8]       = c[mt][nt][2];
                    sC[(n + 1) * 128 + f0 + 8] = c[mt][nt][3];
                }
            }
        }
        __syncthreads();
        float* mp = C + (size_t)bb * MELS * TF + t0;
        #pragma unroll
        for (int i = 0; i < 10; i++) {
            int flat = tid + i * 256;
            int m = flat >> 5, q = flat & 31;
            float4 v = *(float4*)(sC + m * 128 + q * 4);
            float bm = __ldg(bias + m);
            v.x += bm; v.y += bm; v.z += bm; v.w += bm;
            *(float4*)(mp + (size_t)m * TF + q * 4) = v;
        }
    }
    #undef LOADG
    #undef STAGE
    #undef COMPUTE
}

// ---------------------------------------------------------------------------
__global__ void dur_kernel(const float* __restrict__ W_dur,
                           const float* __restrict__ b_dur,
                           float* __restrict__ out_dur) {
    int row = blockIdx.x;
    float acc = 0.0f;
    const float* e = g_enc + (size_t)row * DD;
    for (int d = threadIdx.x; d < DD; d += 128) acc += e[d] * W_dur[d];
    #pragma unroll
    for (int o = 16; o; o >>= 1) acc += __shfl_down_sync(0xffffffffu, acc, o);
    __shared__ float s[4];
    if ((threadIdx.x & 31) == 0) s[threadIdx.x >> 5] = acc;
    __syncthreads();
    if (threadIdx.x == 0) out_dur[row] = s[0] + s[1] + s[2] + s[3] + b_dur[0];
}

__global__ void tok_kernel(const int* __restrict__ dur) {
    int b = blockIdx.x;
    __shared__ int cs[LL];
    int l = threadIdx.x;
    cs[l] = dur[b * LL + l];
    __syncthreads();
    for (int off = 1; off < LL; off <<= 1) {
        int v = (l >= off) ? cs[l - off] : 0;
        __syncthreads();
        cs[l] += v;
        __syncthreads();
    }
    for (int t = threadIdx.x; t < TF; t += 256) {
        int lo = 0, hi = LL;
        while (lo < hi) {
            int mid = (lo + hi) >> 1;
            if (cs[mid] <= t) lo = mid + 1; else hi = mid;
        }
        g_tok[b * TF + t] = (lo < LL) ? lo : -1;
    }
}

// ---------------------------------------------------------------------------
extern "C" void kernel_launch(void* const* d_in, const int* in_sizes, int n_in,
                              void* d_out, int out_size) {
    const int*   src   = (const int*)d_in[0];
    const int*   durin = (const int*)d_in[1];
    const float* emb   = (const float*)d_in[3];
    const float* pos   = (const float*)d_in[4];
    const float* W_enc = (const float*)d_in[5];
    const float* b_enc = (const float*)d_in[6];
    const float* W_dur = (const float*)d_in[7];
    const float* b_dur = (const float*)d_in[8];
    const float* W_dec = (const float*)d_in[9];
    const float* b_dec = (const float*)d_in[10];
    const float* W_gen = (const float*)d_in[11];
    const float* b_gen = (const float*)d_in[12];

    float* out     = (float*)d_out;
    float* mel     = out;
    float* dur_out = out + MEL_ELEMS;

    float* gx;   cudaGetSymbolAddress((void**)&gx,   g_x);
    float* genc; cudaGetSymbolAddress((void**)&genc, g_enc);
    float* gdec; cudaGetSymbolAddress((void**)&gdec, g_dec);
    unsigned* wef; cudaGetSymbolAddress((void**)&wef, g_WencF);
    unsigned* wdf; cudaGetSymbolAddress((void**)&wdf, g_WdecF);
    unsigned* wgf; cudaGetSymbolAddress((void**)&wgf, g_WgenF);

    const int SMEM = 71680;
    cudaFuncSetAttribute(mma_gemm<false, false>,
                         cudaFuncAttributeMaxDynamicSharedMemorySize, SMEM);
    cudaFuncSetAttribute(mma_gemm<true, false>,
                         cudaFuncAttributeMaxDynamicSharedMemorySize, SMEM);
    cudaFuncSetAttribute(mma_gemm<false, true>,
                         cudaFuncAttributeMaxDynamicSharedMemorySize, SMEM);

    // 0-2: fragment-order weights; 3: cvec; 4: embed
    wfrag_kernel<<<4 * KC_N, 256>>>(W_enc, wef, DD);
    wfrag_kernel<<<4 * KC_N, 256>>>(W_dec, wdf, DD);
    wfrag_kernel<<<1 * KC_N, 256>>>(W_gen, wgf, MELS);
    cvec_kernel<<<MELS, 128>>>(b_dec, W_gen, b_gen);
    embed_kernel<<<BB * LL, 128>>>(src, emb, pos);

    // 5: enc = relu(x @ W_enc + b_enc)
    mma_gemm<false, false><<<dim3(4, (BB * LL) / 128), 256, SMEM>>>(gx, (unsigned*)wef, b_enc, genc);

    dur_kernel<<<BB * LL, 128>>>(W_dur, b_dur, dur_out);
    tok_kernel<<<BB, LL>>>(durin);

    // dec = relu(gather(enc) @ W_dec + b_dec), valid tiles only
    mma_gemm<true, false><<<dim3(4, M2 / 128), 256, SMEM>>>(nullptr, (unsigned*)wdf, b_dec, gdec);

    // mel = transpose(dec @ W_gen + b_gen); invalid tiles -> cvec
    mma_gemm<false, true><<<dim3(1, M2 / 128), 256, SMEM>>>(gdec, (unsigned*)wgf, b_gen, mel);
}

// round 6
// speedup vs baseline: 5.5867x; 1.6244x over previous
#include <cuda_runtime.h>
#include <cuda_fp16.h>
#include <cstdint>

// Problem constants
#define BB 16
#define LL 256
#define DD 512
#define MELS 80
#define TF 3072
#define M2 (BB * TF)
#define MEL_ELEMS (BB * MELS * TF)
#define KC_N (DD / 32)        // 16 K-chunks of 32
#define FRAG_W 2048           // fp16 fragment block: 128n x 32k = 8 KB (words)

// Scratch (device globals; no allocations allowed)
__device__ unsigned g_xh[BB * LL * (DD / 2)];      // embed+pos, fp16x2 packed
__device__ float    g_enc[BB * LL * DD];           // encoder out (fp32; dur needs it)
__device__ unsigned g_dech[(size_t)M2 * (DD / 2)]; // decoder out, fp16x2 packed
__device__ int      g_tok[M2];                     // frame -> token (-1 invalid)
__device__ unsigned g_WencF[4 * KC_N * FRAG_W];    // fragment-order fp16 weights
__device__ unsigned g_WdecF[4 * KC_N * FRAG_W];
__device__ unsigned g_WgenF[1 * KC_N * FRAG_W];    // n>=80 zero-padded
__device__ float    g_cvec[MELS];                  // relu(b_dec) @ W_gen + b_gen

__device__ __forceinline__ unsigned pkh2(float lo, float hi) {
    __half2 h = __floats2half2_rn(lo, hi);  // .x = lo
    return *(unsigned*)&h;
}
__device__ __forceinline__ void mma16f(float c[4], const unsigned a[4], const unsigned b[2]) {
    asm volatile(
        "mma.sync.aligned.m16n8k16.row.col.f32.f16.f16.f32 "
        "{%0,%1,%2,%3}, {%4,%5,%6,%7}, {%8,%9}, {%0,%1,%2,%3};"
        : "+f"(c[0]), "+f"(c[1]), "+f"(c[2]), "+f"(c[3])
        : "r"(a[0]), "r"(a[1]), "r"(a[2]), "r"(a[3]), "r"(b[0]), "r"(b[1]));
}

// ---------------------------------------------------------------------------
// embed + positional -> packed fp16
__global__ void embed_kernel(const int* __restrict__ src,
                             const float* __restrict__ emb,
                             const float* __restrict__ pos) {
    int row = blockIdx.x;
    int l = row & (LL - 1);
    int v = src[row];
    int d = threadIdx.x * 4;
    float4 e = *(const float4*)(emb + (size_t)v * DD + d);
    float4 p = *(const float4*)(pos + (size_t)l * DD + d);
    uint2 o = make_uint2(pkh2(e.x + p.x, e.y + p.y), pkh2(e.z + p.z, e.w + p.w));
    *(uint2*)(g_xh + (size_t)row * (DD / 2) + threadIdx.x * 2) = o;
}

// ---------------------------------------------------------------------------
// All three fragment-order fp16 weight builds in ONE launch.
// Per chunk block (ntile, kc): 2048 words:
//   w = ((nt*2 + ks)*32 + lane)*2 + r
//   n = ntile*128 + nt*8 + (lane>>2)
//   k = kc*32 + ks*16 + 2*(lane&3) + 8*r      (word packs k, k+1)
__device__ __forceinline__ void wfrag_block(const float* __restrict__ W,
                                            unsigned* __restrict__ out,
                                            int ntile, int Ncols) {
    for (int w = threadIdx.x; w < FRAG_W; w += 256) {
        int r = w & 1, lane = (w >> 1) & 31, ks = (w >> 6) & 1, nt = w >> 7;
        int n = ntile * 128 + nt * 8 + (lane >> 2);
        int k = (blockIdx.x % KC_N) * 32 + ks * 16 + 2 * (lane & 3) + 8 * r;
        float lo = 0.f, hi = 0.f;
        if (n < Ncols) {
            lo = W[(size_t)k * Ncols + n];
            hi = W[(size_t)(k + 1) * Ncols + n];
        }
        out[w] = pkh2(lo, hi);
    }
}
__global__ void prep_w(const float* __restrict__ W_enc,
                       const float* __restrict__ W_dec,
                       const float* __restrict__ W_gen) {
    int blk = blockIdx.x;
    if (blk < 64) {
        wfrag_block(W_enc, g_WencF + (size_t)blk * FRAG_W, blk / KC_N, DD);
    } else if (blk < 128) {
        int b2 = blk - 64;
        wfrag_block(W_dec, g_WdecF + (size_t)b2 * FRAG_W, b2 / KC_N, DD);
    } else {
        int b3 = blk - 128;
        wfrag_block(W_gen, g_WgenF + (size_t)b3 * FRAG_W, 0, MELS);
    }
}

// cvec[m] = relu(b_dec) . W_gen[:,m] + b_gen[m]
__global__ void cvec_kernel(const float* __restrict__ b_dec,
                            const float* __restrict__ W_gen,
                            const float* __restrict__ b_gen) {
    int m = blockIdx.x;
    float acc = 0.0f;
    for (int k = threadIdx.x; k < DD; k += 128)
        acc += fmaxf(b_dec[k], 0.0f) * W_gen[k * MELS + m];
    #pragma unroll
    for (int o = 16; o; o >>= 1) acc += __shfl_down_sync(0xffffffffu, acc, o);
    __shared__ float s[4];
    if ((threadIdx.x & 31) == 0) s[threadIdx.x >> 5] = acc;
    __syncthreads();
    if (threadIdx.x == 0) g_cvec[m] = s[0] + s[1] + s[2] + s[3] + b_gen[m];
}

// ---------------------------------------------------------------------------
// fp16 mma.sync GEMM (m16n8k16), CTA 128x128, 8 warps (2m x 4n), warp 64x32.
// A smem: 128 rows x 20 words (pitch 40 fp16) -> conflict-free fragment LDS.
// B smem: contiguous precomputed fragment block copies.
// GATHER: A = gathered g_enc rows (fp32 -> fp16); else A = packed fp16 rows.
// OUTH:   C stored as packed fp16 (dec). GEN: N=80 transposed mel epilogue.
#define A_P2 20
#define A_BY (128 * A_P2 * 4)   // 10240
#define B_BY (FRAG_W * 4)       // 8192
#define SMEM_SZ 49152           // max(2*(A_BY+B_BY)=36864, GEN sC 40960)

template <bool GATHER, bool GEN, bool OUTH>
__global__ __launch_bounds__(256)
void mma_gemm(const void* __restrict__ Ain, const unsigned* __restrict__ WF,
              const float* __restrict__ bias, void* __restrict__ Cout) {
    extern __shared__ unsigned char sraw[];
    const int tid = threadIdx.x;
    const int lane = tid & 31, wid = tid >> 5;
    const int wm = wid & 1, wn = wid >> 1;
    const int g = lane >> 2, ct = lane & 3;
    const int r0 = blockIdx.y * 128;
    const int ntile = GEN ? 0 : blockIdx.x;

    int bb = 0, t0 = 0;
    if (GEN) {
        bb = r0 / TF; t0 = r0 % TF;
        if (g_tok[r0] < 0) {
            float* mp = (float*)Cout + (size_t)bb * MELS * TF + t0;
            for (int idx = tid; idx < MELS * 128; idx += 256) {
                int m = idx >> 7, f = idx & 127;
                mp[(size_t)m * TF + f] = g_cvec[m];
            }
            return;
        }
    }
    if (GATHER && g_tok[r0] < 0) return;

    unsigned* const As0 = (unsigned*)sraw;
    unsigned* const As1 = (unsigned*)(sraw + A_BY);
    unsigned* const Bs0 = (unsigned*)(sraw + 2 * A_BY);
    unsigned* const Bs1 = (unsigned*)(sraw + 2 * A_BY + B_BY);

    // staging: thread pair per A row (half = k 0..15 or 16..31)
    const int srow = tid >> 1;
    const int half = tid & 1;
    const float*    ArowF = nullptr;
    const unsigned* ArowH = nullptr;
    if (GATHER) {
        int r = r0 + srow;
        int tk = g_tok[r];
        ArowF = (tk >= 0) ? ((const float*)Ain + ((size_t)(r / TF) * LL + tk) * DD)
                          : nullptr;
    } else {
        ArowH = (const unsigned*)Ain + (size_t)(r0 + srow) * (DD / 2);
    }
    const unsigned* WFbase = WF + (size_t)ntile * KC_N * FRAG_W;

    float c[4][4][4];
    #pragma unroll
    for (int mt = 0; mt < 4; mt++)
        #pragma unroll
        for (int nt = 0; nt < 4; nt++)
            #pragma unroll
            for (int j = 0; j < 4; j++) c[mt][nt][j] = 0.0f;

    float4 av[4];
    uint4  ah[2];
    uint4  bv[2];

    #define LOADG(kc)                                                            \
        do {                                                                     \
            const unsigned* bsrc = WFbase + (size_t)(kc) * FRAG_W;               \
            bv[0] = *(const uint4*)(bsrc + (tid) * 4 * 2);                       \
            bv[1] = *(const uint4*)(bsrc + (tid + 256) * 4 * 2 - 256 * 4);       \
            bv[0] = *(const uint4*)(bsrc + tid * 4);                             \
            bv[1] = *(const uint4*)(bsrc + (tid + 256) * 4);                     \
            if (GATHER) {                                                        \
                _Pragma("unroll")                                                \
                for (int i = 0; i < 4; i++)                                      \
                    av[i] = ArowF                                                \
                        ? *(const float4*)(ArowF + (kc) * 32 + half * 16 + i * 4)\
                        : make_float4(0.f, 0.f, 0.f, 0.f);                       \
            } else {                                                             \
                _Pragma("unroll")                                                \
                for (int i = 0; i < 2; i++)                                      \
                    ah[i] = *(const uint4*)(ArowH + (kc) * 16 + half * 8 + i * 4);\
            }                                                                    \
        } while (0)

    #define STAGE(As, Bs)                                                        \
        do {                                                                     \
            if (GATHER) {                                                        \
                ah[0] = make_uint4(pkh2(av[0].x, av[0].y), pkh2(av[0].z, av[0].w),\
                                   pkh2(av[1].x, av[1].y), pkh2(av[1].z, av[1].w));\
                ah[1] = make_uint4(pkh2(av[2].x, av[2].y), pkh2(av[2].z, av[2].w),\
                                   pkh2(av[3].x, av[3].y), pkh2(av[3].z, av[3].w));\
            }                                                                    \
            *(uint4*)(As + srow * A_P2 + half * 8)     = ah[0];                  \
            *(uint4*)(As + srow * A_P2 + half * 8 + 4) = ah[1];                  \
            *(uint4*)(Bs + tid * 4)         = bv[0];                             \
            *(uint4*)(Bs + (tid + 256) * 4) = bv[1];                             \
        } while (0)

    #define COMPUTE(As, Bs)                                                      \
        do {                                                                     \
            _Pragma("unroll")                                                    \
            for (int ks = 0; ks < 2; ks++) {                                     \
                unsigned af[4][4], bf[4][2];                                     \
                _Pragma("unroll")                                                \
                for (int mt = 0; mt < 4; mt++) {                                 \
                    const unsigned* ap =                                         \
                        As + (wm * 64 + mt * 16 + g) * A_P2 + ks * 8 + ct;       \
                    af[mt][0] = ap[0];                                           \
                    af[mt][1] = ap[8 * A_P2];                                    \
                    af[mt][2] = ap[4];                                           \
                    af[mt][3] = ap[8 * A_P2 + 4];                                \
                }                                                                \
                _Pragma("unroll")                                                \
                for (int nt = 0; nt < 4; nt++)                                   \
                    *(uint2*)bf[nt] = *(const uint2*)(Bs +                       \
                        (((wn * 4 + nt) * 2 + ks) * 32 + lane) * 2);             \
                _Pragma("unroll")                                                \
                for (int mt = 0; mt < 4; mt++)                                   \
                    _Pragma("unroll")                                            \
                    for (int nt = 0; nt < 4; nt++)                               \
                        mma16f(c[mt][nt], af[mt], bf[nt]);                       \
            }                                                                    \
        } while (0)

    LOADG(0);
    STAGE(As0, Bs0);
    __syncthreads();

    #pragma unroll 2
    for (int kc = 0; kc < KC_N; kc++) {
        if (kc + 1 < KC_N) LOADG(kc + 1);
        if (kc & 1) COMPUTE(As1, Bs1); else COMPUTE(As0, Bs0);
        if (kc + 1 < KC_N) {
            if ((kc + 1) & 1) STAGE(As1, Bs1); else STAGE(As0, Bs0);
            __syncthreads();
        }
    }

    if (GEN) {
        // transpose through smem, coalesced mel[b][m][t] stores
        __syncthreads();
        float* sC = (float*)sraw;  // [80][128] = 40 KB
        #pragma unroll
        for (int mt = 0; mt < 4; mt++) {
            int f0 = wm * 64 + mt * 16 + g;
            #pragma unroll
            for (int nt = 0; nt < 4; nt++) {
                int n = wn * 32 + nt * 8 + ct * 2;
                if (n < MELS) {
                    sC[n * 128 + f0]           = c[mt][nt][0];
                    sC[(n + 1) * 128 + f0]     = c[mt][nt][1];
                    sC[n * 128 + f0 + 8]       = c[mt][nt][2];
                    sC[(n + 1) * 128 + f0 + 8] = c[mt][nt][3];
                }
            }
        }
        __syncthreads();
        float* mp = (float*)Cout + (size_t)bb * MELS * TF + t0;
        #pragma unroll
        for (int i = 0; i < 10; i++) {
            int flat = tid + i * 256;
            int m = flat >> 5, q = flat & 31;
            float4 v = *(float4*)(sC + m * 128 + q * 4);
            float bm = __ldg(bias + m);
            v.x += bm; v.y += bm; v.z += bm; v.w += bm;
            *(float4*)(mp + (size_t)m * TF + q * 4) = v;
        }
    } else if (OUTH) {
        // dec: relu + pack fp16x2
        unsigned* Ch = (unsigned*)Cout;
        #pragma unroll
        for (int mt = 0; mt < 4; mt++) {
            int row0 = r0 + wm * 64 + mt * 16 + g;
            unsigned* C0 = Ch + (size_t)row0 * (DD / 2);
            unsigned* C1 = C0 + (size_t)8 * (DD / 2);
            #pragma unroll
            for (int nt = 0; nt < 4; nt++) {
                int n = ntile * 128 + wn * 32 + nt * 8 + ct * 2;
                float b0 = __ldg(bias + n), b1 = __ldg(bias + n + 1);
                C0[n >> 1] = pkh2(fmaxf(c[mt][nt][0] + b0, 0.f),
                                  fmaxf(c[mt][nt][1] + b1, 0.f));
                C1[n >> 1] = pkh2(fmaxf(c[mt][nt][2] + b0, 0.f),
                                  fmaxf(c[mt][nt][3] + b1, 0.f));
            }
        }
    } else {
        // enc: relu, fp32 out
        float* Cf = (float*)Cout;
        #pragma unroll
        for (int mt = 0; mt < 4; mt++) {
            int row0 = r0 + wm * 64 + mt * 16 + g;
            float* C0 = Cf + (size_t)row0 * DD;
            float* C1 = C0 + (size_t)8 * DD;
            #pragma unroll
            for (int nt = 0; nt < 4; nt++) {
                int n = ntile * 128 + wn * 32 + nt * 8 + ct * 2;
                float b0 = __ldg(bias + n), b1 = __ldg(bias + n + 1);
                *(float2*)(C0 + n) = make_float2(fmaxf(c[mt][nt][0] + b0, 0.f),
                                                 fmaxf(c[mt][nt][1] + b1, 0.f));
                *(float2*)(C1 + n) = make_float2(fmaxf(c[mt][nt][2] + b0, 0.f),
                                                 fmaxf(c[mt][nt][3] + b1, 0.f));
            }
        }
    }
    #undef LOADG
    #undef STAGE
    #undef COMPUTE
}

// ---------------------------------------------------------------------------
__global__ void dur_kernel(const float* __restrict__ W_dur,
                           const float* __restrict__ b_dur,
                           float* __restrict__ out_dur) {
    int row = blockIdx.x;
    float acc = 0.0f;
    const float* e = g_enc + (size_t)row * DD;
    for (int d = threadIdx.x; d < DD; d += 128) acc += e[d] * W_dur[d];
    #pragma unroll
    for (int o = 16; o; o >>= 1) acc += __shfl_down_sync(0xffffffffu, acc, o);
    __shared__ float s[4];
    if ((threadIdx.x & 31) == 0) s[threadIdx.x >> 5] = acc;
    __syncthreads();
    if (threadIdx.x == 0) out_dur[row] = s[0] + s[1] + s[2] + s[3] + b_dur[0];
}

__global__ void tok_kernel(const int* __restrict__ dur) {
    int b = blockIdx.x;
    __shared__ int cs[LL];
    int l = threadIdx.x;
    cs[l] = dur[b * LL + l];
    __syncthreads();
    for (int off = 1; off < LL; off <<= 1) {
        int v = (l >= off) ? cs[l - off] : 0;
        __syncthreads();
        cs[l] += v;
        __syncthreads();
    }
    for (int t = threadIdx.x; t < TF; t += 256) {
        int lo = 0, hi = LL;
        while (lo < hi) {
            int mid = (lo + hi) >> 1;
            if (cs[mid] <= t) lo = mid + 1; else hi = mid;
        }
        g_tok[b * TF + t] = (lo < LL) ? lo : -1;
    }
}

// ---------------------------------------------------------------------------
extern "C" void kernel_launch(void* const* d_in, const int* in_sizes, int n_in,
                              void* d_out, int out_size) {
    const int*   src   = (const int*)d_in[0];
    const int*   durin = (const int*)d_in[1];
    const float* emb   = (const float*)d_in[3];
    const float* pos   = (const float*)d_in[4];
    const float* W_enc = (const float*)d_in[5];
    const float* b_enc = (const float*)d_in[6];
    const float* W_dur = (const float*)d_in[7];
    const float* b_dur = (const float*)d_in[8];
    const float* W_dec = (const float*)d_in[9];
    const float* b_dec = (const float*)d_in[10];
    const float* W_gen = (const float*)d_in[11];
    const float* b_gen = (const float*)d_in[12];

    float* out     = (float*)d_out;
    float* mel     = out;
    float* dur_out = out + MEL_ELEMS;

    unsigned* gxh;  cudaGetSymbolAddress((void**)&gxh,  g_xh);
    float*    genc; cudaGetSymbolAddress((void**)&genc, g_enc);
    unsigned* gdh;  cudaGetSymbolAddress((void**)&gdh,  g_dech);
    unsigned* wef;  cudaGetSymbolAddress((void**)&wef,  g_WencF);
    unsigned* wdf;  cudaGetSymbolAddress((void**)&wdf,  g_WdecF);
    unsigned* wgf;  cudaGetSymbolAddress((void**)&wgf,  g_WgenF);

    cudaFuncSetAttribute(mma_gemm<false, false, false>,
                         cudaFuncAttributeMaxDynamicSharedMemorySize, SMEM_SZ);
    cudaFuncSetAttribute(mma_gemm<true, false, true>,
                         cudaFuncAttributeMaxDynamicSharedMemorySize, SMEM_SZ);
    cudaFuncSetAttribute(mma_gemm<false, true, false>,
                         cudaFuncAttributeMaxDynamicSharedMemorySize, SMEM_SZ);

    prep_w<<<144, 256>>>(W_enc, W_dec, W_gen);
    cvec_kernel<<<MELS, 128>>>(b_dec, W_gen, b_gen);
    embed_kernel<<<BB * LL, 128>>>(src, emb, pos);

    // enc = relu(x @ W_enc + b_enc)
    mma_gemm<false, false, false><<<dim3(4, (BB * LL) / 128), 256, SMEM_SZ>>>(
        gxh, wef, b_enc, genc);

    dur_kernel<<<BB * LL, 128>>>(W_dur, b_dur, dur_out);
    tok_kernel<<<BB, LL>>>(durin);

    // dec = relu(gather(enc) @ W_dec + b_dec) -> packed fp16, valid tiles only
    mma_gemm<true, false, true><<<dim3(4, M2 / 128), 256, SMEM_SZ>>>(
        genc, wdf, b_dec, gdh);

    // mel = transpose(dec @ W_gen + b_gen); invalid tiles -> cvec
    mma_gemm<false, true, false><<<dim3(1, M2 / 128), 256, SMEM_SZ>>>(
        gdh, wgf, b_gen, mel);
}

// round 9
// speedup vs baseline: 6.5300x; 1.1688x over previous
#include <cuda_runtime.h>
#include <cuda_fp16.h>
#include <cstdint>

// Problem constants
#define BB 16
#define LL 256
#define DD 512
#define MELS 80
#define TF 3072
#define M2 (BB * TF)
#define MEL_ELEMS (BB * MELS * TF)
#define KC_N (DD / 32)        // 16 K-chunks of 32
#define FRAG_W 2048           // fp16 fragment block: 128n x 32k = 8 KB (words)

// Scratch (device globals; no allocations allowed)
__device__ unsigned g_xh[BB * LL * (DD / 2)];      // embed+pos, fp16x2
__device__ float    g_enc[BB * LL * DD];           // encoder out fp32 (dur head)
__device__ unsigned g_ench[BB * LL * (DD / 2)];    // encoder out fp16x2 (dec input)
__device__ unsigned g_dech[(size_t)M2 * (DD / 2)]; // decoder out fp16x2
__device__ int      g_tok[M2];                     // frame -> token (-1 invalid)
__device__ unsigned g_WencF[4 * KC_N * FRAG_W];    // fragment-order fp16 weights
__device__ unsigned g_WdecF[4 * KC_N * FRAG_W];
__device__ unsigned g_WgenF[1 * KC_N * FRAG_W];    // n>=80 zero-padded
__device__ float    g_cvec[MELS];                  // relu(b_dec) @ W_gen + b_gen

__device__ __forceinline__ unsigned pkh2(float lo, float hi) {
    __half2 h = __floats2half2_rn(lo, hi);
    return *(unsigned*)&h;
}
__device__ __forceinline__ void mma16f(float c[4], const unsigned a[4], const unsigned b[2]) {
    asm volatile(
        "mma.sync.aligned.m16n8k16.row.col.f32.f16.f16.f32 "
        "{%0,%1,%2,%3}, {%4,%5,%6,%7}, {%8,%9}, {%0,%1,%2,%3};"
        : "+f"(c[0]), "+f"(c[1]), "+f"(c[2]), "+f"(c[3])
        : "r"(a[0]), "r"(a[1]), "r"(a[2]), "r"(a[3]), "r"(b[0]), "r"(b[1]));
}
__device__ __forceinline__ void ldmx4(unsigned r[4], unsigned saddr) {
    asm volatile("ldmatrix.sync.aligned.m8n8.x4.shared.b16 {%0,%1,%2,%3}, [%4];"
                 : "=r"(r[0]), "=r"(r[1]), "=r"(r[2]), "=r"(r[3]) : "r"(saddr));
}
__device__ __forceinline__ void cp16(unsigned dst, const void* src, unsigned sz) {
    asm volatile("cp.async.cg.shared.global [%0], [%1], 16, %2;"
                 :: "r"(dst), "l"(src), "r"(sz));
}
__device__ __forceinline__ void cp_commit() {
    asm volatile("cp.async.commit_group;" ::: "memory");
}
template <int N>
__device__ __forceinline__ void cp_wait() {
    asm volatile("cp.async.wait_group %0;" :: "n"(N) : "memory");
}

// ---------------------------------------------------------------------------
// Fused prologue: fragment-order weights (blocks 0..143), cvec (144..223),
// embed+pos -> fp16 (224..2271).
__device__ __forceinline__ void wfrag_block(const float* __restrict__ W,
                                            unsigned* __restrict__ out,
                                            int ntile, int kc, int Ncols) {
    for (int w = threadIdx.x; w < FRAG_W; w += 256) {
        int r = w & 1, lane = (w >> 1) & 31, ks = (w >> 6) & 1, nt = w >> 7;
        int n = ntile * 128 + nt * 8 + (lane >> 2);
        int k = kc * 32 + ks * 16 + 2 * (lane & 3) + 8 * r;
        float lo = 0.f, hi = 0.f;
        if (n < Ncols) {
            lo = W[(size_t)k * Ncols + n];
            hi = W[(size_t)(k + 1) * Ncols + n];
        }
        out[w] = pkh2(lo, hi);
    }
}
__global__ void prep_kernel(const float* __restrict__ W_enc,
                            const float* __restrict__ W_dec,
                            const float* __restrict__ W_gen,
                            const float* __restrict__ b_dec,
                            const float* __restrict__ b_gen,
                            const int* __restrict__ src,
                            const float* __restrict__ emb,
                            const float* __restrict__ pos) {
    int blk = blockIdx.x;
    int tid = threadIdx.x;
    if (blk < 144) {
        if (blk < 64)
            wfrag_block(W_enc, g_WencF + (size_t)blk * FRAG_W, blk / KC_N, blk % KC_N, DD);
        else if (blk < 128) {
            int b2 = blk - 64;
            wfrag_block(W_dec, g_WdecF + (size_t)b2 * FRAG_W, b2 / KC_N, b2 % KC_N, DD);
        } else {
            int b3 = blk - 128;
            wfrag_block(W_gen, g_WgenF + (size_t)b3 * FRAG_W, 0, b3 % KC_N, MELS);
        }
    } else if (blk < 224) {
        int m = blk - 144;
        float acc = 0.0f;
        for (int k = tid; k < DD; k += 256)
            acc += fmaxf(b_dec[k], 0.0f) * W_gen[k * MELS + m];
        #pragma unroll
        for (int o = 16; o; o >>= 1) acc += __shfl_down_sync(0xffffffffu, acc, o);
        __shared__ float s[8];
        if ((tid & 31) == 0) s[tid >> 5] = acc;
        __syncthreads();
        if (tid == 0) {
            float t = b_gen[m];
            #pragma unroll
            for (int i = 0; i < 8; i++) t += s[i];
            g_cvec[m] = t;
        }
    } else {
        int idx = blk - 224;                 // 0..2047, 2 rows each
        int row = idx * 2 + (tid >> 7);
        int l = row & (LL - 1);
        int v = src[row];
        int d = (tid & 127) * 4;
        float4 e = *(const float4*)(emb + (size_t)v * DD + d);
        float4 p = *(const float4*)(pos + (size_t)l * DD + d);
        *(uint2*)(g_xh + (size_t)row * (DD / 2) + (tid & 127) * 2) =
            make_uint2(pkh2(e.x + p.x, e.y + p.y), pkh2(e.z + p.z, e.w + p.w));
    }
}

// ---------------------------------------------------------------------------
// fp16 mma.sync GEMM (m16n8k16), CTA 128x128, 8 warps (2m x 4n), warp 64x32.
// cp.async 3-stage pipeline; A fragments via ldmatrix.x4 (pitch-20-word rows,
// conflict-free); B fragments precomputed in register order (LDS.64).
// MODE 0 = enc (A=g_xh; out fp32 g_enc + fp16 g_ench)
// MODE 1 = dec (A=gather(g_ench) w/ zfill; skip invalid tiles; out fp16)
// MODE 2 = gen (A=g_dech; N=80; transposed mel; invalid tiles -> cvec)
#define A_P2 20                         // words per A row (40 halfs, 4 pad)
#define A_BY (128 * A_P2 * 4)           // 10240
#define B_BY (FRAG_W * 4)               // 8192
#define STG_BY (A_BY + B_BY)            // 18432
#define SMEM_SZ (3 * STG_BY)            // 55296 (>= GEN sC 40960)

template <int MODE>
__global__ __launch_bounds__(256)
void mma_gemm(const unsigned* __restrict__ Ain, const unsigned* __restrict__ WF,
              const float* __restrict__ bias, void* __restrict__ Cout,
              void* __restrict__ Cout2) {
    extern __shared__ unsigned char sraw[];
    const int tid = threadIdx.x;
    const int lane = tid & 31, wid = tid >> 5;
    const int wm = wid & 1, wn = wid >> 1;
    const int g = lane >> 2, ct = lane & 3;
    const int r0 = blockIdx.y * 128;
    const int ntile = (MODE == 2) ? 0 : blockIdx.x;

    int bb = 0, t0 = 0;
    if (MODE == 2) {
        bb = r0 / TF; t0 = r0 % TF;
        if (g_tok[r0] < 0) {
            float* mp = (float*)Cout + (size_t)bb * MELS * TF + t0;
            for (int idx = tid; idx < MELS * 128; idx += 256) {
                int m = idx >> 7, f = idx & 127;
                mp[(size_t)m * TF + f] = g_cvec[m];
            }
            return;
        }
    }
    if (MODE == 1 && g_tok[r0] < 0) return;

    const unsigned sbase = (unsigned)__cvta_generic_to_shared(sraw);

    // cp.async source/dest mapping: thread pair per A row; B contiguous copy
    const int srow = tid >> 1, half = tid & 1;
    const unsigned* arow;
    unsigned asz = 16;
    if (MODE == 1) {
        int r = r0 + srow;
        int tk = g_tok[r];
        if (tk >= 0) arow = g_ench + ((size_t)(r / TF) * LL + tk) * (DD / 2);
        else { arow = g_ench; asz = 0; }           // zero-fill row
    } else {
        arow = Ain + (size_t)(r0 + srow) * (DD / 2);
    }
    arow += half * 8;
    const unsigned adst = (srow * A_P2 + half * 8) * 4;
    const unsigned* bsrc0 = WF + (size_t)ntile * KC_N * FRAG_W + tid * 8;
    const unsigned bdst = A_BY + tid * 32;

    // ldmatrix lane addressing for A fragments
    const int lm = lane >> 3, rr = lane & 7;
    unsigned arow_w[4];
    #pragma unroll
    for (int mt = 0; mt < 4; mt++)
        arow_w[mt] = (unsigned)((wm * 64 + mt * 16 + (lm & 1) * 8 + rr) * A_P2 +
                                (lm >> 1) * 4);

    float c[4][4][4];
    #pragma unroll
    for (int mt = 0; mt < 4; mt++)
        #pragma unroll
        for (int nt = 0; nt < 4; nt++)
            #pragma unroll
            for (int j = 0; j < 4; j++) c[mt][nt][j] = 0.0f;

    #define ISSUE(kc, s)                                                   \
        do {                                                               \
            unsigned st = sbase + (s) * STG_BY;                            \
            cp16(st + adst, arow + (kc) * 16, asz);                        \
            cp16(st + adst + 16, arow + (kc) * 16 + 4, asz);               \
            const unsigned* bp = bsrc0 + (size_t)(kc) * FRAG_W;            \
            cp16(st + bdst, bp, 16);                                       \
            cp16(st + bdst + 16, bp + 4, 16);                              \
            cp_commit();                                                   \
        } while (0)

    #define COMPUTE(s)                                                    \
        do {                                                              \
            unsigned ab = sbase + (s) * STG_BY;                           \
            const uint2* Bp = (const uint2*)(sraw + (s) * STG_BY + A_BY); \
            _Pragma("unroll")                                             \
            for (int ks = 0; ks < 2; ks++) {                              \
                unsigned af[4][4], bf[4][2];                              \
                _Pragma("unroll")                                         \
                for (int mt = 0; mt < 4; mt++)                            \
                    ldmx4(af[mt], ab + (arow_w[mt] + ks * 8) * 4);        \
                _Pragma("unroll")                                         \
                for (int nt = 0; nt < 4; nt++)                            \
                    *(uint2*)bf[nt] =                                     \
                        Bp[((wn * 4 + nt) * 2 + ks) * 32 + lane];         \
                _Pragma("unroll")                                         \
                for (int mt = 0; mt < 4; mt++)                            \
                    _Pragma("unroll")                                     \
                    for (int nt = 0; nt < 4; nt++)                        \
                        mma16f(c[mt][nt], af[mt], bf[nt]);                \
            }                                                             \
        } while (0)

    ISSUE(0, 0);
    ISSUE(1, 1);
    #pragma unroll 4
    for (int kc = 0; kc < KC_N; kc++) {
        if (kc + 2 < KC_N) cp_wait<1>(); else cp_wait<0>();
        __syncthreads();
        COMPUTE(kc % 3);
        if (kc + 2 < KC_N) ISSUE(kc + 2, (kc + 2) % 3);
    }
    #undef ISSUE
    #undef COMPUTE

    if (MODE == 2) {
        __syncthreads();
        float* sC = (float*)sraw;  // [80][128] = 40 KB
        #pragma unroll
        for (int mt = 0; mt < 4; mt++) {
            int f0 = wm * 64 + mt * 16 + g;
            #pragma unroll
            for (int nt = 0; nt < 4; nt++) {
                int n = wn * 32 + nt * 8 + ct * 2;
                if (n < MELS) {
                    sC[n * 128 + f0]           = c[mt][nt][0];
                    sC[(n + 1) * 128 + f0]     = c[mt][nt][1];
                    sC[n * 128 + f0 + 8]       = c[mt][nt][2];
                    sC[(n + 1) * 128 + f0 + 8] = c[mt][nt][3];
                }
            }
        }
        __syncthreads();
        float* mp = (float*)Cout + (size_t)bb * MELS * TF + t0;
        #pragma unroll
        for (int i = 0; i < 10; i++) {
            int flat = tid + i * 256;
            int m = flat >> 5, q = flat & 31;
            float4 v = *(float4*)(sC + m * 128 + q * 4);
            float bm = __ldg(bias + m);
            v.x += bm; v.y += bm; v.z += bm; v.w += bm;
            *(float4*)(mp + (size_t)m * TF + q * 4) = v;
        }
    } else if (MODE == 1) {
        unsigned* Ch = (unsigned*)Cout;
        #pragma unroll
        for (int mt = 0; mt < 4; mt++) {
            int row0 = r0 + wm * 64 + mt * 16 + g;
            unsigned* C0 = Ch + (size_t)row0 * (DD / 2);
            unsigned* C1 = C0 + (size_t)8 * (DD / 2);
            #pragma unroll
            for (int nt = 0; nt < 4; nt++) {
                int n = ntile * 128 + wn * 32 + nt * 8 + ct * 2;
                float b0 = __ldg(bias + n), b1 = __ldg(bias + n + 1);
                C0[n >> 1] = pkh2(fmaxf(c[mt][nt][0] + b0, 0.f),
                                  fmaxf(c[mt][nt][1] + b1, 0.f));
                C1[n >> 1] = pkh2(fmaxf(c[mt][nt][2] + b0, 0.f),
                                  fmaxf(c[mt][nt][3] + b1, 0.f));
            }
        }
    } else {
        float*    Cf = (float*)Cout;
        unsigned* Ch = (unsigned*)Cout2;
        #pragma unroll
        for (int mt = 0; mt < 4; mt++) {
            int row0 = r0 + wm * 64 + mt * 16 + g;
            float*    C0 = Cf + (size_t)row0 * DD;
            float*    C1 = C0 + (size_t)8 * DD;
            unsigned* H0 = Ch + (size_t)row0 * (DD / 2);
            unsigned* H1 = H0 + (size_t)8 * (DD / 2);
            #pragma unroll
            for (int nt = 0; nt < 4; nt++) {
                int n = ntile * 128 + wn * 32 + nt * 8 + ct * 2;
                float b0 = __ldg(bias + n), b1 = __ldg(bias + n + 1);
                float v0 = fmaxf(c[mt][nt][0] + b0, 0.f);
                float v1 = fmaxf(c[mt][nt][1] + b1, 0.f);
                float v2 = fmaxf(c[mt][nt][2] + b0, 0.f);
                float v3 = fmaxf(c[mt][nt][3] + b1, 0.f);
                *(float2*)(C0 + n) = make_float2(v0, v1);
                *(float2*)(C1 + n) = make_float2(v2, v3);
                H0[n >> 1] = pkh2(v0, v1);
                H1[n >> 1] = pkh2(v2, v3);
            }
        }
    }
}

// ---------------------------------------------------------------------------
__global__ void dur_kernel(const float* __restrict__ W_dur,
                           const float* __restrict__ b_dur,
                           float* __restrict__ out_dur) {
    int row = blockIdx.x;
    float acc = 0.0f;
    const float* e = g_enc + (size_t)row * DD;
    for (int d = threadIdx.x; d < DD; d += 128) acc += e[d] * W_dur[d];
    #pragma unroll
    for (int o = 16; o; o >>= 1) acc += __shfl_down_sync(0xffffffffu, acc, o);
    __shared__ float s[4];
    if ((threadIdx.x & 31) == 0) s[threadIdx.x >> 5] = acc;
    __syncthreads();
    if (threadIdx.x == 0) out_dur[row] = s[0] + s[1] + s[2] + s[3] + b_dur[0];
}

__global__ void tok_kernel(const int* __restrict__ dur) {
    int b = blockIdx.x;
    __shared__ int cs[LL];
    int l = threadIdx.x;
    cs[l] = dur[b * LL + l];
    __syncthreads();
    for (int off = 1; off < LL; off <<= 1) {
        int v = (l >= off) ? cs[l - off] : 0;
        __syncthreads();
        cs[l] += v;
        __syncthreads();
    }
    for (int t = threadIdx.x; t < TF; t += 256) {
        int lo = 0, hi = LL;
        while (lo < hi) {
            int mid = (lo + hi) >> 1;
            if (cs[mid] <= t) lo = mid + 1; else hi = mid;
        }
        g_tok[b * TF + t] = (lo < LL) ? lo : -1;
    }
}

// ---------------------------------------------------------------------------
extern "C" void kernel_launch(void* const* d_in, const int* in_sizes, int n_in,
                              void* d_out, int out_size) {
    const int*   src   = (const int*)d_in[0];
    const int*   durin = (const int*)d_in[1];
    const float* emb   = (const float*)d_in[3];
    const float* pos   = (const float*)d_in[4];
    const float* W_enc = (const float*)d_in[5];
    const float* b_enc = (const float*)d_in[6];
    const float* W_dur = (const float*)d_in[7];
    const float* b_dur = (const float*)d_in[8];
    const float* W_dec = (const float*)d_in[9];
    const float* b_dec = (const float*)d_in[10];
    const float* W_gen = (const float*)d_in[11];
    const float* b_gen = (const float*)d_in[12];

    float* out     = (float*)d_out;
    float* mel     = out;
    float* dur_out = out + MEL_ELEMS;

    unsigned* gxh;  cudaGetSymbolAddress((void**)&gxh,  g_xh);
    float*    genc; cudaGetSymbolAddress((void**)&genc, g_enc);
    unsigned* geh;  cudaGetSymbolAddress((void**)&geh,  g_ench);
    unsigned* gdh;  cudaGetSymbolAddress((void**)&gdh,  g_dech);
    unsigned* wef;  cudaGetSymbolAddress((void**)&wef,  g_WencF);
    unsigned* wdf;  cudaGetSymbolAddress((void**)&wdf,  g_WdecF);
    unsigned* wgf;  cudaGetSymbolAddress((void**)&wgf,  g_WgenF);

    cudaFuncSetAttribute(mma_gemm<0>, cudaFuncAttributeMaxDynamicSharedMemorySize, SMEM_SZ);
    cudaFuncSetAttribute(mma_gemm<1>, cudaFuncAttributeMaxDynamicSharedMemorySize, SMEM_SZ);
    cudaFuncSetAttribute(mma_gemm<2>, cudaFuncAttributeMaxDynamicSharedMemorySize, SMEM_SZ);

    // fused prologue + early token map (overlaps enc)
    prep_kernel<<<2272, 256>>>(W_enc, W_dec, W_gen, b_dec, b_gen, src, emb, pos);
    tok_kernel<<<BB, LL>>>(durin);

    // enc = relu(x @ W_enc + b_enc) -> fp32 + fp16
    mma_gemm<0><<<dim3(4, (BB * LL) / 128), 256, SMEM_SZ>>>(gxh, wef, b_enc, genc, geh);

    dur_kernel<<<BB * LL, 128>>>(W_dur, b_dur, dur_out);

    // dec = relu(gather(enc) @ W_dec + b_dec) -> fp16, valid tiles only
    mma_gemm<1><<<dim3(4, M2 / 128), 256, SMEM_SZ>>>(geh, wdf, b_dec, gdh, nullptr);

    // mel = transpose(dec @ W_gen + b_gen); invalid tiles -> cvec
    mma_gemm<2><<<dim3(1, M2 / 128), 256, SMEM_SZ>>>(gdh, wgf, b_gen, mel, nullptr);
}

// round 10
// speedup vs baseline: 7.0767x; 1.0837x over previous
#include <cuda_runtime.h>
#include <cuda_fp16.h>
#include <cstdint>

// Problem constants
#define BB 16
#define LL 256
#define DD 512
#define MELS 80
#define TF 3072
#define M2 (BB * TF)
#define MEL_ELEMS (BB * MELS * TF)
#define KC_N (DD / 32)        // 16 K-chunks of 32
#define FRAG_W 2048           // fp16 fragment block: 128n x 32k = 8 KB (words)

// Scratch (device globals; no allocations allowed)
__device__ unsigned g_xh[BB * LL * (DD / 2)];      // embed+pos, fp16x2
__device__ unsigned g_ench[BB * LL * (DD / 2)];    // encoder out fp16x2
__device__ unsigned g_dech[(size_t)M2 * (DD / 2)]; // decoder out fp16x2
__device__ int      g_tok[M2];                     // frame -> token (-1 invalid)
__device__ int      g_csum[BB * LL];               // per-batch duration cumsum
__device__ float    g_durp[BB * LL * 16];          // dur-head partials [row][ntile*4+wn]
__device__ unsigned g_WencF[4 * KC_N * FRAG_W];    // fragment-order fp16 weights
__device__ unsigned g_WdecF[4 * KC_N * FRAG_W];
__device__ unsigned g_WgenF[1 * KC_N * FRAG_W];    // n>=80 zero-padded
__device__ float    g_cvec[MELS];                  // relu(b_dec) @ W_gen + b_gen

__device__ __forceinline__ unsigned pkh2(float lo, float hi) {
    __half2 h = __floats2half2_rn(lo, hi);
    return *(unsigned*)&h;
}
__device__ __forceinline__ void mma16f(float c[4], const unsigned a[4], const unsigned b[2]) {
    asm volatile(
        "mma.sync.aligned.m16n8k16.row.col.f32.f16.f16.f32 "
        "{%0,%1,%2,%3}, {%4,%5,%6,%7}, {%8,%9}, {%0,%1,%2,%3};"
        : "+f"(c[0]), "+f"(c[1]), "+f"(c[2]), "+f"(c[3])
        : "r"(a[0]), "r"(a[1]), "r"(a[2]), "r"(a[3]), "r"(b[0]), "r"(b[1]));
}
__device__ __forceinline__ void ldmx4(unsigned r[4], unsigned saddr) {
    asm volatile("ldmatrix.sync.aligned.m8n8.x4.shared.b16 {%0,%1,%2,%3}, [%4];"
                 : "=r"(r[0]), "=r"(r[1]), "=r"(r[2]), "=r"(r[3]) : "r"(saddr));
}
__device__ __forceinline__ void cp16(unsigned dst, const void* src, unsigned sz) {
    asm volatile("cp.async.cg.shared.global [%0], [%1], 16, %2;"
                 :: "r"(dst), "l"(src), "r"(sz));
}
__device__ __forceinline__ void cp_commit() {
    asm volatile("cp.async.commit_group;" ::: "memory");
}
template <int N>
__device__ __forceinline__ void cp_wait() {
    asm volatile("cp.async.wait_group %0;" :: "n"(N) : "memory");
}

// ---------------------------------------------------------------------------
// Fused prologue: fragment-order weights (blocks 0..143), cvec (144..223),
// embed+pos -> fp16 (224..2271).
__device__ __forceinline__ void wfrag_block(const float* __restrict__ W,
                                            unsigned* __restrict__ out,
                                            int ntile, int kc, int Ncols) {
    for (int w = threadIdx.x; w < FRAG_W; w += 256) {
        int r = w & 1, lane = (w >> 1) & 31, ks = (w >> 6) & 1, nt = w >> 7;
        int n = ntile * 128 + nt * 8 + (lane >> 2);
        int k = kc * 32 + ks * 16 + 2 * (lane & 3) + 8 * r;
        float lo = 0.f, hi = 0.f;
        if (n < Ncols) {
            lo = W[(size_t)k * Ncols + n];
            hi = W[(size_t)(k + 1) * Ncols + n];
        }
        out[w] = pkh2(lo, hi);
    }
}
__global__ void prep_kernel(const float* __restrict__ W_enc,
                            const float* __restrict__ W_dec,
                            const float* __restrict__ W_gen,
                            const float* __restrict__ b_dec,
                            const float* __restrict__ b_gen,
                            const int* __restrict__ src,
                            const float* __restrict__ emb,
                            const float* __restrict__ pos) {
    int blk = blockIdx.x;
    int tid = threadIdx.x;
    if (blk < 144) {
        if (blk < 64)
            wfrag_block(W_enc, g_WencF + (size_t)blk * FRAG_W, blk / KC_N, blk % KC_N, DD);
        else if (blk < 128) {
            int b2 = blk - 64;
            wfrag_block(W_dec, g_WdecF + (size_t)b2 * FRAG_W, b2 / KC_N, b2 % KC_N, DD);
        } else {
            int b3 = blk - 128;
            wfrag_block(W_gen, g_WgenF + (size_t)b3 * FRAG_W, 0, b3 % KC_N, MELS);
        }
    } else if (blk < 224) {
        int m = blk - 144;
        float acc = 0.0f;
        for (int k = tid; k < DD; k += 256)
            acc += fmaxf(b_dec[k], 0.0f) * W_gen[k * MELS + m];
        #pragma unroll
        for (int o = 16; o; o >>= 1) acc += __shfl_down_sync(0xffffffffu, acc, o);
        __shared__ float s[8];
        if ((tid & 31) == 0) s[tid >> 5] = acc;
        __syncthreads();
        if (tid == 0) {
            float t = b_gen[m];
            #pragma unroll
            for (int i = 0; i < 8; i++) t += s[i];
            g_cvec[m] = t;
        }
    } else {
        int idx = blk - 224;                 // 0..2047, 2 rows each
        int row = idx * 2 + (tid >> 7);
        int l = row & (LL - 1);
        int v = src[row];
        int d = (tid & 127) * 4;
        float4 e = *(const float4*)(emb + (size_t)v * DD + d);
        float4 p = *(const float4*)(pos + (size_t)l * DD + d);
        *(uint2*)(g_xh + (size_t)row * (DD / 2) + (tid & 127) * 2) =
            make_uint2(pkh2(e.x + p.x, e.y + p.y), pkh2(e.z + p.z, e.w + p.w));
    }
}

// ---------------------------------------------------------------------------
// Token map, two stages: per-batch scan then parallel searchsorted fill.
__global__ void tok_scan(const int* __restrict__ dur) {
    int b = blockIdx.x;
    __shared__ int cs[LL];
    int l = threadIdx.x;
    cs[l] = dur[b * LL + l];
    __syncthreads();
    for (int off = 1; off < LL; off <<= 1) {
        int v = (l >= off) ? cs[l - off] : 0;
        __syncthreads();
        cs[l] += v;
        __syncthreads();
    }
    g_csum[b * LL + l] = cs[l];
}
__global__ void tok_fill() {
    int b = blockIdx.x;
    int t = blockIdx.y * 256 + threadIdx.x;
    __shared__ int cs[LL];
    cs[threadIdx.x] = g_csum[b * LL + threadIdx.x];
    __syncthreads();
    int lo = 0, hi = LL;
    while (lo < hi) {
        int mid = (lo + hi) >> 1;
        if (cs[mid] <= t) lo = mid + 1; else hi = mid;
    }
    g_tok[b * TF + t] = (lo < LL) ? lo : -1;
}

// dur finalize: sum 16 partials + b_dur
__global__ void dur_fin(const float* __restrict__ b_dur, float* __restrict__ out) {
    int row = blockIdx.x * 256 + threadIdx.x;   // 0..4095
    float s = b_dur[0];
    const float* p = g_durp + (size_t)row * 16;
    #pragma unroll
    for (int i = 0; i < 16; i++) s += p[i];
    out[row] = s;
}

// ---------------------------------------------------------------------------
// fp16 mma.sync GEMM (m16n8k16), CTA 128x128, 8 warps (2m x 4n), warp 64x32.
// cp.async 3-stage pipeline; A fragments via ldmatrix.x4; B precomputed
// register-order fragments (LDS.64).
// MODE 0 = enc (A=g_xh; out fp16 g_ench + dur-head partials)
// MODE 1 = dec (A=gather(g_ench) w/ zfill; skip invalid tiles; out fp16)
// MODE 2 = gen (A=g_dech; N=80; transposed mel; invalid tiles -> cvec)
#define A_P2 20                         // words per A row (40 halfs, 4 pad)
#define A_BY (128 * A_P2 * 4)           // 10240
#define B_BY (FRAG_W * 4)               // 8192
#define STG_BY (A_BY + B_BY)            // 18432
#define SMEM_SZ (3 * STG_BY)            // 55296 (>= GEN sC 40960)

template <int MODE>
__global__ __launch_bounds__(256)
void mma_gemm(const unsigned* __restrict__ Ain, const unsigned* __restrict__ WF,
              const float* __restrict__ bias, void* __restrict__ Cout,
              const float* __restrict__ Wdur) {
    extern __shared__ unsigned char sraw[];
    const int tid = threadIdx.x;
    const int lane = tid & 31, wid = tid >> 5;
    const int wm = wid & 1, wn = wid >> 1;
    const int g = lane >> 2, ct = lane & 3;
    const int r0 = blockIdx.y * 128;
    const int ntile = (MODE == 2) ? 0 : blockIdx.x;

    int bb = 0, t0 = 0;
    if (MODE == 2) {
        bb = r0 / TF; t0 = r0 % TF;
        if (g_tok[r0] < 0) {
            float* mp = (float*)Cout + (size_t)bb * MELS * TF + t0;
            for (int idx = tid; idx < MELS * 128; idx += 256) {
                int m = idx >> 7, f = idx & 127;
                mp[(size_t)m * TF + f] = g_cvec[m];
            }
            return;
        }
    }
    if (MODE == 1 && g_tok[r0] < 0) return;

    const unsigned sbase = (unsigned)__cvta_generic_to_shared(sraw);

    // cp.async source/dest mapping: thread pair per A row; B contiguous copy
    const int srow = tid >> 1, half = tid & 1;
    const unsigned* arow;
    unsigned asz = 16;
    if (MODE == 1) {
        int r = r0 + srow;
        int tk = g_tok[r];
        if (tk >= 0) arow = g_ench + ((size_t)(r / TF) * LL + tk) * (DD / 2);
        else { arow = g_ench; asz = 0; }           // zero-fill row
    } else {
        arow = Ain + (size_t)(r0 + srow) * (DD / 2);
    }
    arow += half * 8;
    const unsigned adst = (srow * A_P2 + half * 8) * 4;
    const unsigned* bsrc0 = WF + (size_t)ntile * KC_N * FRAG_W + tid * 8;
    const unsigned bdst = A_BY + tid * 32;

    // ldmatrix lane addressing for A fragments
    const int lm = lane >> 3, rr = lane & 7;
    unsigned arow_w[4];
    #pragma unroll
    for (int mt = 0; mt < 4; mt++)
        arow_w[mt] = (unsigned)((wm * 64 + mt * 16 + (lm & 1) * 8 + rr) * A_P2 +
                                (lm >> 1) * 4);

    float c[4][4][4];
    #pragma unroll
    for (int mt = 0; mt < 4; mt++)
        #pragma unroll
        for (int nt = 0; nt < 4; nt++)
            #pragma unroll
            for (int j = 0; j < 4; j++) c[mt][nt][j] = 0.0f;

    #define ISSUE(kc, s)                                                   \
        do {                                                               \
            unsigned st = sbase + (s) * STG_BY;                            \
            cp16(st + adst, arow + (kc) * 16, asz);                        \
            cp16(st + adst + 16, arow + (kc) * 16 + 4, asz);               \
            const unsigned* bp = bsrc0 + (size_t)(kc) * FRAG_W;            \
            cp16(st + bdst, bp, 16);                                       \
            cp16(st + bdst + 16, bp + 4, 16);                              \
            cp_commit();                                                   \
        } while (0)

    #define COMPUTE(s)                                                    \
        do {                                                              \
            unsigned ab = sbase + (s) * STG_BY;                           \
            const uint2* Bp = (const uint2*)(sraw + (s) * STG_BY + A_BY); \
            _Pragma("unroll")                                             \
            for (int ks = 0; ks < 2; ks++) {                              \
                unsigned af[4][4], bf[4][2];                              \
                _Pragma("unroll")                                         \
                for (int mt = 0; mt < 4; mt++)                            \
                    ldmx4(af[mt], ab + (arow_w[mt] + ks * 8) * 4);        \
                _Pragma("unroll")                                         \
                for (int nt = 0; nt < 4; nt++)                            \
                    *(uint2*)bf[nt] =                                     \
                        Bp[((wn * 4 + nt) * 2 + ks) * 32 + lane];         \
                _Pragma("unroll")                                         \
                for (int mt = 0; mt < 4; mt++)                            \
                    _Pragma("unroll")                                     \
                    for (int nt = 0; nt < 4; nt++)                        \
                        mma16f(c[mt][nt], af[mt], bf[nt]);                \
            }                                                             \
        } while (0)

    ISSUE(0, 0);
    ISSUE(1, 1);
    #pragma unroll 4
    for (int kc = 0; kc < KC_N; kc++) {
        if (kc + 2 < KC_N) cp_wait<1>(); else cp_wait<0>();
        __syncthreads();
        COMPUTE(kc % 3);
        if (kc + 2 < KC_N) ISSUE(kc + 2, (kc + 2) % 3);
    }
    #undef ISSUE
    #undef COMPUTE

    if (MODE == 2) {
        __syncthreads();
        float* sC = (float*)sraw;  // [80][128] = 40 KB
        #pragma unroll
        for (int mt = 0; mt < 4; mt++) {
            int f0 = wm * 64 + mt * 16 + g;
            #pragma unroll
            for (int nt = 0; nt < 4; nt++) {
                int n = wn * 32 + nt * 8 + ct * 2;
                if (n < MELS) {
                    sC[n * 128 + f0]           = c[mt][nt][0];
                    sC[(n + 1) * 128 + f0]     = c[mt][nt][1];
                    sC[n * 128 + f0 + 8]       = c[mt][nt][2];
                    sC[(n + 1) * 128 + f0 + 8] = c[mt][nt][3];
                }
            }
        }
        __syncthreads();
        float* mp = (float*)Cout + (size_t)bb * MELS * TF + t0;
        #pragma unroll
        for (int i = 0; i < 10; i++) {
            int flat = tid + i * 256;
            int m = flat >> 5, q = flat & 31;
            float4 v = *(float4*)(sC + m * 128 + q * 4);
            float bm = __ldg(bias + m);
            v.x += bm; v.y += bm; v.z += bm; v.w += bm;
            *(float4*)(mp + (size_t)m * TF + q * 4) = v;
        }
    } else if (MODE == 1) {
        unsigned* Ch = (unsigned*)Cout;
        #pragma unroll
        for (int mt = 0; mt < 4; mt++) {
            int row0 = r0 + wm * 64 + mt * 16 + g;
            unsigned* C0 = Ch + (size_t)row0 * (DD / 2);
            unsigned* C1 = C0 + (size_t)8 * (DD / 2);
            #pragma unroll
            for (int nt = 0; nt < 4; nt++) {
                int n = ntile * 128 + wn * 32 + nt * 8 + ct * 2;
                float b0 = __ldg(bias + n), b1 = __ldg(bias + n + 1);
                C0[n >> 1] = pkh2(fmaxf(c[mt][nt][0] + b0, 0.f),
                                  fmaxf(c[mt][nt][1] + b1, 0.f));
                C1[n >> 1] = pkh2(fmaxf(c[mt][nt][2] + b0, 0.f),
                                  fmaxf(c[mt][nt][3] + b1, 0.f));
            }
        }
    } else {
        // enc: relu -> fp16 out + duration-head partials (fp32, deterministic)
        unsigned* Ch = (unsigned*)Cout;
        #pragma unroll
        for (int mt = 0; mt < 4; mt++) {
            int row0 = r0 + wm * 64 + mt * 16 + g;
            unsigned* C0 = Ch + (size_t)row0 * (DD / 2);
            unsigned* C1 = C0 + (size_t)8 * (DD / 2);
            float dp0 = 0.f, dp1 = 0.f;
            #pragma unroll
            for (int nt = 0; nt < 4; nt++) {
                int n = ntile * 128 + wn * 32 + nt * 8 + ct * 2;
                float b0 = __ldg(bias + n), b1 = __ldg(bias + n + 1);
                float v0 = fmaxf(c[mt][nt][0] + b0, 0.f);
                float v1 = fmaxf(c[mt][nt][1] + b1, 0.f);
                float v2 = fmaxf(c[mt][nt][2] + b0, 0.f);
                float v3 = fmaxf(c[mt][nt][3] + b1, 0.f);
                C0[n >> 1] = pkh2(v0, v1);
                C1[n >> 1] = pkh2(v2, v3);
                float w0 = __ldg(Wdur + n), w1 = __ldg(Wdur + n + 1);
                dp0 += v0 * w0 + v1 * w1;
                dp1 += v2 * w0 + v3 * w1;
            }
            // quad reduce over ct lanes (same g)
            dp0 += __shfl_xor_sync(0xffffffffu, dp0, 1);
            dp0 += __shfl_xor_sync(0xffffffffu, dp0, 2);
            dp1 += __shfl_xor_sync(0xffffffffu, dp1, 1);
            dp1 += __shfl_xor_sync(0xffffffffu, dp1, 2);
            if (ct == 0) {
                g_durp[(size_t)row0 * 16 + ntile * 4 + wn] = dp0;
                g_durp[(size_t)(row0 + 8) * 16 + ntile * 4 + wn] = dp1;
            }
        }
    }
}

// ---------------------------------------------------------------------------
extern "C" void kernel_launch(void* const* d_in, const int* in_sizes, int n_in,
                              void* d_out, int out_size) {
    const int*   src   = (const int*)d_in[0];
    const int*   durin = (const int*)d_in[1];
    const float* emb   = (const float*)d_in[3];
    const float* pos   = (const float*)d_in[4];
    const float* W_enc = (const float*)d_in[5];
    const float* b_enc = (const float*)d_in[6];
    const float* W_dur = (const float*)d_in[7];
    const float* b_dur = (const float*)d_in[8];
    const float* W_dec = (const float*)d_in[9];
    const float* b_dec = (const float*)d_in[10];
    const float* W_gen = (const float*)d_in[11];
    const float* b_gen = (const float*)d_in[12];

    float* out     = (float*)d_out;
    float* mel     = out;
    float* dur_out = out + MEL_ELEMS;

    unsigned* gxh;  cudaGetSymbolAddress((void**)&gxh,  g_xh);
    unsigned* geh;  cudaGetSymbolAddress((void**)&geh,  g_ench);
    unsigned* gdh;  cudaGetSymbolAddress((void**)&gdh,  g_dech);
    unsigned* wef;  cudaGetSymbolAddress((void**)&wef,  g_WencF);
    unsigned* wdf;  cudaGetSymbolAddress((void**)&wdf,  g_WdecF);
    unsigned* wgf;  cudaGetSymbolAddress((void**)&wgf,  g_WgenF);

    cudaFuncSetAttribute(mma_gemm<0>, cudaFuncAttributeMaxDynamicSharedMemorySize, SMEM_SZ);
    cudaFuncSetAttribute(mma_gemm<1>, cudaFuncAttributeMaxDynamicSharedMemorySize, SMEM_SZ);
    cudaFuncSetAttribute(mma_gemm<2>, cudaFuncAttributeMaxDynamicSharedMemorySize, SMEM_SZ);

    // prologue (weights, cvec, embed) + token map
    prep_kernel<<<2272, 256>>>(W_enc, W_dec, W_gen, b_dec, b_gen, src, emb, pos);
    tok_scan<<<BB, LL>>>(durin);
    tok_fill<<<dim3(BB, TF / 256), 256>>>();

    // enc = relu(x @ W_enc + b_enc) -> fp16 + dur partials
    mma_gemm<0><<<dim3(4, (BB * LL) / 128), 256, SMEM_SZ>>>(gxh, wef, b_enc, geh, W_dur);

    // dur_pred = partials sum + b_dur
    dur_fin<<<BB * LL / 256, 256>>>(b_dur, dur_out);

    // dec = relu(gather(enc) @ W_dec + b_dec) -> fp16, valid tiles only
    mma_gemm<1><<<dim3(4, M2 / 128), 256, SMEM_SZ>>>(geh, wdf, b_dec, gdh, nullptr);

    // mel = transpose(dec @ W_gen + b_gen); invalid tiles -> cvec
    mma_gemm<2><<<dim3(1, M2 / 128), 256, SMEM_SZ>>>(gdh, wgf, b_gen, mel, nullptr);
}